// round 1
// baseline (speedup 1.0000x reference)
#include <cuda_runtime.h>

// Shapes (fixed by the problem):
//   x: (4,16,256,128) fp32  -> 16384 rows x 128 ch
//   w_qkv: (128,384), w_out: (128,128), b_out: (128)
//   16 (b,head) attention pairs, seq N=4096, dh=32, SCALE=10 (folded into K)

#define SEQ   4096
#define DH    32
#define NPAIR 16

// Scratch (device globals: no allocation allowed in kernel_launch)
__device__ float g_KT[NPAIR * DH * SEQ];   // [pair][dh][i]  k, l2-normed over heads, *10
__device__ float g_VT[NPAIR * DH * SEQ];   // [pair][dh][j]
__device__ float g_V [NPAIR * SEQ * DH];   // [pair][j][dh]
__device__ float g_O [4 * SEQ * 128];      // attention out, already in (b,spatial,c) layout

// ---------------------------------------------------------------------------
// Kernel 1: kv projection + head-group l2 norm + scatter into attention layout
// ---------------------------------------------------------------------------
__global__ __launch_bounds__(256) void proj_kv_kernel(const float* __restrict__ x,
                                                      const float* __restrict__ w_qkv) {
    __shared__ float xsh[128][36];   // [k][row], pitch 36 keeps float4 rows aligned
    const int row0 = blockIdx.x * 32;
    const int tid  = threadIdx.x;

    for (int idx = tid; idx < 32 * 128; idx += 256) {
        int r = idx >> 7, k = idx & 127;
        xsh[k][r] = x[(row0 + r) * 128 + k];
    }
    __syncthreads();

    const int c = tid;                       // 0..255: k channels 0..127, v channels 0..127
    float acc[32];
#pragma unroll
    for (int r = 0; r < 32; r++) acc[r] = 0.f;

    const float* wp = w_qkv + 128 + c;       // k cols = 128..255, v cols = 256..383
    for (int k = 0; k < 128; k++) {
        float w = wp[k * 384];
#pragma unroll
        for (int r4 = 0; r4 < 8; r4++) {
            float4 a = *(const float4*)&xsh[k][r4 * 4];
            acc[r4 * 4 + 0] += a.x * w;
            acc[r4 * 4 + 1] += a.y * w;
            acc[r4 * 4 + 2] += a.z * w;
            acc[r4 * 4 + 3] += a.w * w;
        }
    }

    const bool is_k = (c < 128);
    const int  cc   = is_k ? c : (c - 128);
    const int  h    = cc & 3;
    const int  g    = cc >> 2;

#pragma unroll
    for (int r = 0; r < 32; r++) {
        int sg = row0 + r;
        int b  = sg >> 12;
        int sp = sg & 4095;
        int dh = sp >> 7;
        int i  = ((sp & 127) << 5) + g;
        int pair = (b << 2) + h;
        float val = acc[r];
        if (is_k) {
            // l2 norm over the 4 heads = channels {4g..4g+3} (adjacent lanes)
            float ss = val * val;
            ss += __shfl_xor_sync(0xffffffffu, ss, 1);
            ss += __shfl_xor_sync(0xffffffffu, ss, 2);
            float nrm = sqrtf(ss);
            float kv  = val / fmaxf(nrm, 1e-12f) * 10.f;   // SCALE folded in
            g_KT[(pair * DH + dh) * SEQ + i] = kv;
        } else {
            g_VT[(pair * DH + dh) * SEQ + i] = val;
            g_V [(pair * SEQ + i) * DH + dh] = val;
        }
    }
}

// ---------------------------------------------------------------------------
// Kernel 2: flash attention, 64x64 tiles, fp32 register GEMMs
// 128 threads = 16(ty: 4 i-rows each) x 8(tx: 8 j-cols / 4 dh each)
// ---------------------------------------------------------------------------
__global__ __launch_bounds__(128) void attn_kernel() {
    __shared__ float Ksh [DH][64];   // [dh][i]
    __shared__ float VshT[DH][64];   // [dh][j]
    __shared__ float Vsh [64][DH];   // [j][dh]
    __shared__ float Psh [64][64];   // [j][i]

    const int p  = blockIdx.y;
    const int i0 = blockIdx.x * 64;
    const float* KT = g_KT + p * DH * SEQ;
    const float* VT = g_VT + p * DH * SEQ;
    const float* Vp = g_V  + p * SEQ * DH;

    const int tid = threadIdx.x;
    const int tx  = tid & 7;
    const int ty  = tid >> 3;

    // Load K tile once (float4 along i, coalesced from [dh][i] layout)
    for (int idx = tid; idx < DH * 16; idx += 128) {
        int dh = idx >> 4, i4 = idx & 15;
        *(float4*)&Ksh[dh][i4 * 4] = *(const float4*)&KT[dh * SEQ + i0 + i4 * 4];
    }

    float m[4], l[4], acc[4][4];
#pragma unroll
    for (int r = 0; r < 4; r++) {
        m[r] = -1e30f; l[r] = 0.f;
#pragma unroll
        for (int q = 0; q < 4; q++) acc[r][q] = 0.f;
    }

    for (int j0 = 0; j0 < SEQ; j0 += 64) {
        __syncthreads();   // protect Vsh/VshT/Psh from prior-iter readers
        for (int idx = tid; idx < DH * 16; idx += 128) {
            int dh = idx >> 4, j4 = idx & 15;
            *(float4*)&VshT[dh][j4 * 4] = *(const float4*)&VT[dh * SEQ + j0 + j4 * 4];
        }
        for (int idx = tid; idx < 64 * 8; idx += 128) {
            int j = idx >> 3, d4 = idx & 7;
            *(float4*)&Vsh[j][d4 * 4] = *(const float4*)&Vp[(j0 + j) * DH + d4 * 4];
        }
        __syncthreads();

        // S = K_i^T V_j  (S already includes SCALE via K)
        float S[4][8];
#pragma unroll
        for (int r = 0; r < 4; r++)
#pragma unroll
            for (int cq = 0; cq < 8; cq++) S[r][cq] = 0.f;

#pragma unroll 8
        for (int kk = 0; kk < DH; kk++) {
            float4 a  = *(const float4*)&Ksh[kk][ty * 4];
            float4 b0 = *(const float4*)&VshT[kk][tx * 8];
            float4 b1 = *(const float4*)&VshT[kk][tx * 8 + 4];
            float av[4] = {a.x, a.y, a.z, a.w};
            float bv[8] = {b0.x, b0.y, b0.z, b0.w, b1.x, b1.y, b1.z, b1.w};
#pragma unroll
            for (int r = 0; r < 4; r++)
#pragma unroll
                for (int cq = 0; cq < 8; cq++) S[r][cq] += av[r] * bv[cq];
        }

        // online softmax over j (row groups share 8 consecutive lanes -> shfl)
#pragma unroll
        for (int r = 0; r < 4; r++) {
            float mx = S[r][0];
#pragma unroll
            for (int cq = 1; cq < 8; cq++) mx = fmaxf(mx, S[r][cq]);
            mx = fmaxf(mx, __shfl_xor_sync(0xffffffffu, mx, 1));
            mx = fmaxf(mx, __shfl_xor_sync(0xffffffffu, mx, 2));
            mx = fmaxf(mx, __shfl_xor_sync(0xffffffffu, mx, 4));
            float mnew  = fmaxf(m[r], mx);
            float alpha = __expf(m[r] - mnew);
            m[r] = mnew;
            float rs = 0.f;
#pragma unroll
            for (int cq = 0; cq < 8; cq++) {
                S[r][cq] = __expf(S[r][cq] - mnew);
                rs += S[r][cq];
            }
            rs += __shfl_xor_sync(0xffffffffu, rs, 1);
            rs += __shfl_xor_sync(0xffffffffu, rs, 2);
            rs += __shfl_xor_sync(0xffffffffu, rs, 4);
            l[r] = l[r] * alpha + rs;
#pragma unroll
            for (int q = 0; q < 4; q++) acc[r][q] *= alpha;
        }

        // write P transposed [j][i] (float4 over the 4 contiguous i-rows)
#pragma unroll
        for (int cq = 0; cq < 8; cq++) {
            float4 pv = make_float4(S[0][cq], S[1][cq], S[2][cq], S[3][cq]);
            *(float4*)&Psh[tx * 8 + cq][ty * 4] = pv;
        }
        __syncthreads();

        // acc += P^T V_j
#pragma unroll 8
        for (int kk = 0; kk < 64; kk++) {
            float4 a = *(const float4*)&Psh[kk][ty * 4];
            float4 b = *(const float4*)&Vsh[kk][tx * 4];
            float av[4] = {a.x, a.y, a.z, a.w};
            float bv[4] = {b.x, b.y, b.z, b.w};
#pragma unroll
            for (int r = 0; r < 4; r++)
#pragma unroll
                for (int q = 0; q < 4; q++) acc[r][q] += av[r] * bv[q];
        }
    }

    // epilogue: out[b, i, dh*4+h] = acc / l
    const int b = p >> 2, h = p & 3;
#pragma unroll
    for (int r = 0; r < 4; r++) {
        float inv = 1.f / l[r];
        int i = i0 + ty * 4 + r;
        float* op = g_O + (b * SEQ + i) * 128 + h;
#pragma unroll
        for (int q = 0; q < 4; q++) {
            int dh = tx * 4 + q;
            op[dh * 4] = acc[r][q] * inv;
        }
    }
}

// ---------------------------------------------------------------------------
// Kernel 3: y = O @ w_out + b_out
// ---------------------------------------------------------------------------
__global__ __launch_bounds__(128) void proj_out_kernel(const float* __restrict__ w_out,
                                                       const float* __restrict__ b_out,
                                                       float* __restrict__ y) {
    __shared__ float osh[128][36];
    const int row0 = blockIdx.x * 32;
    const int tid  = threadIdx.x;

    for (int idx = tid; idx < 32 * 128; idx += 128) {
        int r = idx >> 7, k = idx & 127;
        osh[k][r] = g_O[(row0 + r) * 128 + k];
    }
    __syncthreads();

    const int c = tid;   // 128 output channels
    float acc[32];
#pragma unroll
    for (int r = 0; r < 32; r++) acc[r] = 0.f;

    for (int k = 0; k < 128; k++) {
        float w = w_out[k * 128 + c];
#pragma unroll
        for (int r4 = 0; r4 < 8; r4++) {
            float4 a = *(const float4*)&osh[k][r4 * 4];
            acc[r4 * 4 + 0] += a.x * w;
            acc[r4 * 4 + 1] += a.y * w;
            acc[r4 * 4 + 2] += a.z * w;
            acc[r4 * 4 + 3] += a.w * w;
        }
    }
    float bias = b_out[c];
#pragma unroll
    for (int r = 0; r < 32; r++)
        y[(row0 + r) * 128 + c] = acc[r] + bias;
}

// ---------------------------------------------------------------------------
extern "C" void kernel_launch(void* const* d_in, const int* in_sizes, int n_in,
                              void* d_out, int out_size) {
    // Identify inputs by element count (robust to metadata ordering)
    const float *x = nullptr, *wq = nullptr, *wo = nullptr, *bo = nullptr;
    for (int idx = 0; idx < n_in; idx++) {
        switch (in_sizes[idx]) {
            case 4 * 16 * 256 * 128: x  = (const float*)d_in[idx]; break;  // 2097152
            case 128 * 384:          wq = (const float*)d_in[idx]; break;  // 49152
            case 128 * 128:          wo = (const float*)d_in[idx]; break;  // 16384
            case 128:                bo = (const float*)d_in[idx]; break;
        }
    }
    float* y = (float*)d_out;

    proj_kv_kernel<<<512, 256>>>(x, wq);
    attn_kernel<<<dim3(64, NPAIR), 128>>>();
    proj_out_kernel<<<512, 128>>>(wo, bo, y);
}

// round 3
// speedup vs baseline: 2.3013x; 2.3013x over previous
#include <cuda_runtime.h>
#include <cuda_bf16.h>

typedef unsigned int uint;

#define SEQ   4096
#define DH    32
#define NPAIR 16

// ---------------------------------------------------------------------------
// Device scratch
// ---------------------------------------------------------------------------
__device__ __nv_bfloat16 g_Kp[NPAIR * SEQ * 64];     // [pair][i][0:32]=Khi(*10,normed) [32:64]=Klo
__device__ __nv_bfloat16 g_Vp[NPAIR * SEQ * 64];     // [pair][j][0:32]=Vhi [32:64]=Vlo
__device__ __nv_bfloat16 g_VThi[NPAIR * DH * SEQ];   // [pair][dh][j]
__device__ __nv_bfloat16 g_VTlo[NPAIR * DH * SEQ];
__device__ float g_O[4 * SEQ * 128];                 // attention out in (b, spatial, c) layout

// ---------------------------------------------------------------------------
// PTX helpers
// ---------------------------------------------------------------------------
__device__ __forceinline__ void cp16(void* dst, const void* src) {
    unsigned d = (unsigned)__cvta_generic_to_shared(dst);
    asm volatile("cp.async.cg.shared.global [%0], [%1], 16;" :: "r"(d), "l"(src));
}
__device__ __forceinline__ void ldsm4(uint* r, const void* p) {
    unsigned a = (unsigned)__cvta_generic_to_shared(p);
    asm volatile("ldmatrix.sync.aligned.m8n8.x4.shared.b16 {%0,%1,%2,%3}, [%4];"
                 : "=r"(r[0]), "=r"(r[1]), "=r"(r[2]), "=r"(r[3]) : "r"(a));
}
__device__ __forceinline__ void ldsm2(uint* r, const void* p) {
    unsigned a = (unsigned)__cvta_generic_to_shared(p);
    asm volatile("ldmatrix.sync.aligned.m8n8.x2.shared.b16 {%0,%1}, [%2];"
                 : "=r"(r[0]), "=r"(r[1]) : "r"(a));
}
__device__ __forceinline__ void mma16816(float* c, const uint* a, uint b0, uint b1) {
    asm volatile("mma.sync.aligned.m16n8k16.row.col.f32.bf16.bf16.f32 "
                 "{%0,%1,%2,%3},{%4,%5,%6,%7},{%8,%9},{%0,%1,%2,%3};"
                 : "+f"(c[0]), "+f"(c[1]), "+f"(c[2]), "+f"(c[3])
                 : "r"(a[0]), "r"(a[1]), "r"(a[2]), "r"(a[3]), "r"(b0), "r"(b1));
}
__device__ __forceinline__ uint packbf(float x, float y) {
    __nv_bfloat162 t = __floats2bfloat162_rn(x, y);   // .x = x (low half)
    return *(uint*)&t;
}
__device__ __forceinline__ uint packlo(float x, float y, uint hi) {
    __nv_bfloat162 h = *(__nv_bfloat162*)&hi;
    return packbf(x - __bfloat162float(h.x), y - __bfloat162float(h.y));
}

// ---------------------------------------------------------------------------
// Kernel 1: kv projection + head-group l2 norm + bf16 hi/lo split + scatter
// ---------------------------------------------------------------------------
__global__ __launch_bounds__(256) void proj_kv_kernel(const float* __restrict__ x,
                                                      const float* __restrict__ w_qkv) {
    __shared__ float xsh[128][36];
    const int row0 = blockIdx.x * 32;
    const int tid  = threadIdx.x;

    for (int idx = tid; idx < 32 * 128; idx += 256) {
        int r = idx >> 7, k = idx & 127;
        xsh[k][r] = x[(row0 + r) * 128 + k];
    }
    __syncthreads();

    const int c = tid;
    float acc[32];
#pragma unroll
    for (int r = 0; r < 32; r++) acc[r] = 0.f;

    const float* wp = w_qkv + 128 + c;
    for (int k0 = 0; k0 < 128; k0 += 8) {
        float wr[8];
#pragma unroll
        for (int u = 0; u < 8; u++) wr[u] = wp[(k0 + u) * 384];
#pragma unroll
        for (int u = 0; u < 8; u++) {
            int k = k0 + u;
#pragma unroll
            for (int r4 = 0; r4 < 8; r4++) {
                float4 a = *(const float4*)&xsh[k][r4 * 4];
                acc[r4 * 4 + 0] += a.x * wr[u];
                acc[r4 * 4 + 1] += a.y * wr[u];
                acc[r4 * 4 + 2] += a.z * wr[u];
                acc[r4 * 4 + 3] += a.w * wr[u];
            }
        }
    }

    const bool is_k = (c < 128);
    const int  cc   = is_k ? c : (c - 128);
    const int  h    = cc & 3;
    const int  g    = cc >> 2;

#pragma unroll
    for (int r = 0; r < 32; r++) {
        int sg = row0 + r;
        int b  = sg >> 12;
        int sp = sg & 4095;
        int dh = sp >> 7;
        int i  = ((sp & 127) << 5) + g;
        int pair = (b << 2) + h;
        float val = acc[r];
        if (is_k) {
            float ss = val * val;
            ss += __shfl_xor_sync(0xffffffffu, ss, 1);
            ss += __shfl_xor_sync(0xffffffffu, ss, 2);
            float nrm = sqrtf(ss);
            float kv  = val / fmaxf(nrm, 1e-12f) * 10.f;
            __nv_bfloat16 hi = __float2bfloat16_rn(kv);
            __nv_bfloat16 lo = __float2bfloat16_rn(kv - __bfloat162float(hi));
            size_t base = ((size_t)pair * SEQ + i) * 64 + dh;
            g_Kp[base]      = hi;
            g_Kp[base + 32] = lo;
        } else {
            __nv_bfloat16 hi = __float2bfloat16_rn(val);
            __nv_bfloat16 lo = __float2bfloat16_rn(val - __bfloat162float(hi));
            size_t base = ((size_t)pair * SEQ + i) * 64 + dh;
            g_Vp[base]      = hi;
            g_Vp[base + 32] = lo;
            size_t tb = ((size_t)pair * DH + dh) * SEQ + i;
            g_VThi[tb] = hi;
            g_VTlo[tb] = lo;
        }
    }
}

// ---------------------------------------------------------------------------
// Kernel 2: flash attention with bf16 HMMA + hi/lo error compensation.
// Block: 256 threads = 8 warps, 128 i-rows x pair; j-tiles of 128.
// S = [Khi|Khi|Klo](128x96) . [Vhi;Vlo;Vhi](96x128)   (k'=96)
// PV = Phi.Vhi + Phi.Vlo + Plo.Vhi  (S frags reused as A operands, FA2-style)
// ---------------------------------------------------------------------------
#define A_PITCH 104
#define VT_PITCH 136
#define ASH_ELEMS  (128 * A_PITCH)           // 13312
#define BSH_ELEMS  (128 * A_PITCH)           // per stage
#define VT_ELEMS   (DH * VT_PITCH)           // per tensor per stage (4352)
#define SMEM_TOTAL ((ASH_ELEMS + 2 * BSH_ELEMS + 2 * 2 * VT_ELEMS) * 2)   // bytes = 114688

__global__ __launch_bounds__(256, 1) void attn_kernel() {
    extern __shared__ __nv_bfloat16 sm[];
    __nv_bfloat16* Ash = sm;                           // [128][104]
    __nv_bfloat16* Bsh = Ash + ASH_ELEMS;              // [2][128][104]
    __nv_bfloat16* VTs = Bsh + 2 * BSH_ELEMS;          // [2][2][32][136]

    const int p  = blockIdx.y;
    const int i0 = blockIdx.x * 128;
    const int tid  = threadIdx.x;
    const int wid  = tid >> 5;
    const int lane = tid & 31;
    const int mrow = wid * 16;

    // ---- load A' = [Khi|Khi|Klo], rows i0..i0+127 ----
    {
        const uint* Ksrc = (const uint*)(g_Kp + ((size_t)p * SEQ + i0) * 64);  // [128][32 uints]
        uint* AshU = (uint*)Ash;                                               // pitch 52 uints
        for (int idx = tid; idx < 128 * 16; idx += 256) {
            int r = idx >> 4, d = idx & 15;
            uint hi = Ksrc[r * 32 + d];
            uint lo = Ksrc[r * 32 + 16 + d];
            AshU[r * 52 + d]      = hi;
            AshU[r * 52 + 16 + d] = hi;
            AshU[r * 52 + 32 + d] = lo;
        }
    }

    // ---- prefetch stage 0 ----
    const __nv_bfloat16* Vbase  = g_Vp + (size_t)p * SEQ * 64;
    const __nv_bfloat16* VThb   = g_VThi + (size_t)p * DH * SEQ;
    const __nv_bfloat16* VTlb   = g_VTlo + (size_t)p * DH * SEQ;

    auto prefetch = [&](int s, int j0) {
        // B' rows j: [Vhi(0:64B) | Vlo(64:128B of dst <- src 64:128B) | Vhi]
        for (int t = tid; t < 128 * 12; t += 256) {
            int r = t / 12, q = t % 12;
            int srcoff = (q < 4) ? q * 16 : (q < 8) ? 64 + (q - 4) * 16 : (q - 8) * 16;
            const char* src = (const char*)(Vbase + (size_t)(j0 + r) * 64) + srcoff;
            char* dst = (char*)(Bsh + s * BSH_ELEMS + r * A_PITCH) + q * 16;
            cp16(dst, src);
        }
        for (int t = tid; t < 1024; t += 256) {
            int which = t >> 9;
            int rem = t & 511;
            int d = rem >> 4, q = rem & 15;
            const __nv_bfloat16* src = (which ? VTlb : VThb) + (size_t)d * SEQ + j0 + q * 8;
            __nv_bfloat16* dst = VTs + (s * 2 + which) * VT_ELEMS + d * VT_PITCH + q * 8;
            cp16(dst, src);
        }
    };

    prefetch(0, 0);
    asm volatile("cp.async.commit_group;");
    __syncthreads();   // Ash visible

    // ---- per-warp A fragments (constant over j loop) ----
    uint a[6][4];
    {
        int lr = lane & 15, lc = (lane >> 4) * 8;
#pragma unroll
        for (int kt = 0; kt < 6; kt++)
            ldsm4(a[kt], Ash + (mrow + lr) * A_PITCH + kt * 16 + lc);
    }

    float m[2] = {-1e30f, -1e30f}, l[2] = {0.f, 0.f};
    float acc[4][4];
#pragma unroll
    for (int nt = 0; nt < 4; nt++)
#pragma unroll
        for (int e = 0; e < 4; e++) acc[nt][e] = 0.f;

    for (int it = 0; it < 32; it++) {
        int s = it & 1;
        if (it + 1 < 32) prefetch((it + 1) & 1, (it + 1) * 128);
        asm volatile("cp.async.commit_group;");
        asm volatile("cp.async.wait_group 1;");
        __syncthreads();

        // ---- S = A'(16x96) . B'(96x128) per warp ----
        float S[16][4];
#pragma unroll
        for (int jt = 0; jt < 16; jt++)
#pragma unroll
            for (int e = 0; e < 4; e++) S[jt][e] = 0.f;

        const __nv_bfloat16* Bs = Bsh + s * BSH_ELEMS;
#pragma unroll
        for (int kt2 = 0; kt2 < 3; kt2++) {
#pragma unroll
            for (int jt = 0; jt < 16; jt++) {
                uint bfr[4];
                ldsm4(bfr, Bs + (jt * 8 + (lane & 7)) * A_PITCH + kt2 * 32 + (lane >> 3) * 8);
                mma16816(S[jt], a[2 * kt2],     bfr[0], bfr[1]);
                mma16816(S[jt], a[2 * kt2 + 1], bfr[2], bfr[3]);
            }
        }

        // ---- online softmax (rows lane/4 and lane/4+8) ----
#pragma unroll
        for (int r = 0; r < 2; r++) {
            float mx = -1e30f;
#pragma unroll
            for (int jt = 0; jt < 16; jt++)
                mx = fmaxf(mx, fmaxf(S[jt][2 * r], S[jt][2 * r + 1]));
            mx = fmaxf(mx, __shfl_xor_sync(0xffffffffu, mx, 1));
            mx = fmaxf(mx, __shfl_xor_sync(0xffffffffu, mx, 2));
            float mnew  = fmaxf(m[r], mx);
            float alpha = __expf(m[r] - mnew);
            m[r] = mnew;
            float rs = 0.f;
#pragma unroll
            for (int jt = 0; jt < 16; jt++) {
                float e0 = __expf(S[jt][2 * r] - mnew);
                float e1 = __expf(S[jt][2 * r + 1] - mnew);
                S[jt][2 * r] = e0; S[jt][2 * r + 1] = e1;
                rs += e0 + e1;
            }
            rs += __shfl_xor_sync(0xffffffffu, rs, 1);
            rs += __shfl_xor_sync(0xffffffffu, rs, 2);
            l[r] = l[r] * alpha + rs;
#pragma unroll
            for (int nt = 0; nt < 4; nt++) {
                acc[nt][2 * r]     *= alpha;
                acc[nt][2 * r + 1] *= alpha;
            }
        }

        // ---- PV: acc += Phi.Vhi + Phi.Vlo + Plo.Vhi ----
        const __nv_bfloat16* VTh = VTs + (s * 2 + 0) * VT_ELEMS;
        const __nv_bfloat16* VTl = VTs + (s * 2 + 1) * VT_ELEMS;
#pragma unroll
        for (int kt2 = 0; kt2 < 8; kt2++) {
            float* t0 = S[2 * kt2];
            float* t1 = S[2 * kt2 + 1];
            uint ahi[4], alo[4];
            ahi[0] = packbf(t0[0], t0[1]);  alo[0] = packlo(t0[0], t0[1], ahi[0]);
            ahi[1] = packbf(t0[2], t0[3]);  alo[1] = packlo(t0[2], t0[3], ahi[1]);
            ahi[2] = packbf(t1[0], t1[1]);  alo[2] = packlo(t1[0], t1[1], ahi[2]);
            ahi[3] = packbf(t1[2], t1[3]);  alo[3] = packlo(t1[2], t1[3], ahi[3]);
#pragma unroll
            for (int nt = 0; nt < 4; nt++) {
                uint bh[2], bl[2];
                int off = (nt * 8 + (lane & 7)) * VT_PITCH + kt2 * 16 + ((lane >> 3) & 1) * 8;
                ldsm2(bh, VTh + off);
                ldsm2(bl, VTl + off);
                mma16816(acc[nt], ahi, bh[0], bh[1]);
                mma16816(acc[nt], ahi, bl[0], bl[1]);
                mma16816(acc[nt], alo, bh[0], bh[1]);
            }
        }
        __syncthreads();   // stage s fully consumed before it gets overwritten
    }

    // ---- epilogue ----
    const int b = p >> 2, h = p & 3;
    int row0 = i0 + mrow + (lane >> 2);
    int row1 = row0 + 8;
    float inv0 = 1.f / l[0], inv1 = 1.f / l[1];
#pragma unroll
    for (int nt = 0; nt < 4; nt++) {
#pragma unroll
        for (int e = 0; e < 2; e++) {
            int dh = nt * 8 + (lane & 3) * 2 + e;
            g_O[((size_t)b * SEQ + row0) * 128 + dh * 4 + h] = acc[nt][e] * inv0;
            g_O[((size_t)b * SEQ + row1) * 128 + dh * 4 + h] = acc[nt][2 + e] * inv1;
        }
    }
}

// ---------------------------------------------------------------------------
// Kernel 3: y = O @ w_out + b_out
// ---------------------------------------------------------------------------
__global__ __launch_bounds__(128) void proj_out_kernel(const float* __restrict__ w_out,
                                                       const float* __restrict__ b_out,
                                                       float* __restrict__ y) {
    __shared__ float osh[128][36];
    const int row0 = blockIdx.x * 32;
    const int tid  = threadIdx.x;

    for (int idx = tid; idx < 32 * 128; idx += 128) {
        int r = idx >> 7, k = idx & 127;
        osh[k][r] = g_O[(row0 + r) * 128 + k];
    }
    __syncthreads();

    const int c = tid;
    float acc[32];
#pragma unroll
    for (int r = 0; r < 32; r++) acc[r] = 0.f;

    for (int k0 = 0; k0 < 128; k0 += 8) {
        float wr[8];
#pragma unroll
        for (int u = 0; u < 8; u++) wr[u] = w_out[(k0 + u) * 128 + c];
#pragma unroll
        for (int u = 0; u < 8; u++) {
            int k = k0 + u;
#pragma unroll
            for (int r4 = 0; r4 < 8; r4++) {
                float4 a = *(const float4*)&osh[k][r4 * 4];
                acc[r4 * 4 + 0] += a.x * wr[u];
                acc[r4 * 4 + 1] += a.y * wr[u];
                acc[r4 * 4 + 2] += a.z * wr[u];
                acc[r4 * 4 + 3] += a.w * wr[u];
            }
        }
    }
    float bias = b_out[c];
#pragma unroll
    for (int r = 0; r < 32; r++)
        y[(row0 + r) * 128 + c] = acc[r] + bias;
}

// ---------------------------------------------------------------------------
extern "C" void kernel_launch(void* const* d_in, const int* in_sizes, int n_in,
                              void* d_out, int out_size) {
    const float *x = nullptr, *wq = nullptr, *wo = nullptr, *bo = nullptr;
    for (int idx = 0; idx < n_in; idx++) {
        switch (in_sizes[idx]) {
            case 4 * 16 * 256 * 128: x  = (const float*)d_in[idx]; break;
            case 128 * 384:          wq = (const float*)d_in[idx]; break;
            case 128 * 128:          wo = (const float*)d_in[idx]; break;
            case 128:                bo = (const float*)d_in[idx]; break;
        }
    }
    float* y = (float*)d_out;

    cudaFuncSetAttribute(attn_kernel, cudaFuncAttributeMaxDynamicSharedMemorySize, SMEM_TOTAL);

    proj_kv_kernel<<<512, 256>>>(x, wq);
    attn_kernel<<<dim3(32, NPAIR), 256, SMEM_TOTAL>>>();
    proj_out_kernel<<<512, 128>>>(wo, bo, y);
}

// round 8
// speedup vs baseline: 2.5081x; 1.0899x over previous
#include <cuda_runtime.h>
#include <cuda_bf16.h>

typedef unsigned int uint;

#define SEQ   4096
#define DH    32
#define NPAIR 16

// ---------------------------------------------------------------------------
// Device scratch — all transposed layouts [pair][dh][SEQ] for coalesced stores
// ---------------------------------------------------------------------------
__device__ __nv_bfloat16 g_KThi[NPAIR * DH * SEQ];
__device__ __nv_bfloat16 g_KTlo[NPAIR * DH * SEQ];
__device__ __nv_bfloat16 g_VThi[NPAIR * DH * SEQ];
__device__ __nv_bfloat16 g_VTlo[NPAIR * DH * SEQ];
__device__ float g_O[4 * SEQ * 128];

// ---------------------------------------------------------------------------
// PTX helpers
// ---------------------------------------------------------------------------
__device__ __forceinline__ void cp16(void* dst, const void* src) {
    unsigned d = (unsigned)__cvta_generic_to_shared(dst);
    asm volatile("cp.async.cg.shared.global [%0], [%1], 16;" :: "r"(d), "l"(src));
}
__device__ __forceinline__ void ldsm4(uint* r, const void* p) {
    unsigned a = (unsigned)__cvta_generic_to_shared(p);
    asm volatile("ldmatrix.sync.aligned.m8n8.x4.shared.b16 {%0,%1,%2,%3}, [%4];"
                 : "=r"(r[0]), "=r"(r[1]), "=r"(r[2]), "=r"(r[3]) : "r"(a));
}
__device__ __forceinline__ void ldsm4t(uint* r, const void* p) {
    unsigned a = (unsigned)__cvta_generic_to_shared(p);
    asm volatile("ldmatrix.sync.aligned.m8n8.x4.trans.shared.b16 {%0,%1,%2,%3}, [%4];"
                 : "=r"(r[0]), "=r"(r[1]), "=r"(r[2]), "=r"(r[3]) : "r"(a));
}
__device__ __forceinline__ void mma16816(float* c, const uint* a, uint b0, uint b1) {
    asm volatile("mma.sync.aligned.m16n8k16.row.col.f32.bf16.bf16.f32 "
                 "{%0,%1,%2,%3},{%4,%5,%6,%7},{%8,%9},{%0,%1,%2,%3};"
                 : "+f"(c[0]), "+f"(c[1]), "+f"(c[2]), "+f"(c[3])
                 : "r"(a[0]), "r"(a[1]), "r"(a[2]), "r"(a[3]), "r"(b0), "r"(b1));
}
__device__ __forceinline__ uint packbf(float x, float y) {
    __nv_bfloat162 t = __floats2bfloat162_rn(x, y);
    return *(uint*)&t;
}
__device__ __forceinline__ uint packlo(float x, float y, uint hi) {
    __nv_bfloat162 h = *(__nv_bfloat162*)&hi;
    return packbf(x - __bfloat162float(h.x), y - __bfloat162float(h.y));
}

// ---------------------------------------------------------------------------
// Kernel 1: kv projection + l2 norm + hi/lo split; smem-staged coalesced stores
// Block: 32 rows (one b, one dh page), 256 threads (128 K-ch, 128 V-ch)
// ---------------------------------------------------------------------------
#define STG_PITCH 1040                       // 1024 + 16 pad (elements)
#define PROJ_SMEM (16 * STG_PITCH * 2)       // 33280 bytes (also covers xsh 18432)

__global__ __launch_bounds__(256) void proj_kv_kernel(const float* __restrict__ x,
                                                      const float* __restrict__ w_qkv) {
    extern __shared__ char psm[];
    float* xsh = (float*)psm;                          // [128][36]
    __nv_bfloat16* stage = (__nv_bfloat16*)psm;        // [16][1040] (reused after compute)

    const int row0 = blockIdx.x * 32;
    const int tid  = threadIdx.x;

    for (int idx = tid; idx < 32 * 128; idx += 256) {
        int r = idx >> 7, k = idx & 127;
        xsh[k * 36 + r] = x[(row0 + r) * 128 + k];
    }
    __syncthreads();

    const int c = tid;
    float acc[32];
#pragma unroll
    for (int r = 0; r < 32; r++) acc[r] = 0.f;

    const float* wp = w_qkv + 128 + c;
    for (int k0 = 0; k0 < 128; k0 += 8) {
        float wr[8];
#pragma unroll
        for (int u = 0; u < 8; u++) wr[u] = wp[(k0 + u) * 384];
#pragma unroll
        for (int u = 0; u < 8; u++) {
            const float* xr = xsh + (k0 + u) * 36;
#pragma unroll
            for (int r4 = 0; r4 < 8; r4++) {
                float4 a = *(const float4*)&xr[r4 * 4];
                acc[r4 * 4 + 0] += a.x * wr[u];
                acc[r4 * 4 + 1] += a.y * wr[u];
                acc[r4 * 4 + 2] += a.z * wr[u];
                acc[r4 * 4 + 3] += a.w * wr[u];
            }
        }
    }
    __syncthreads();   // done reading xsh; reuse as staging

    const bool is_k = (c < 128);
    const int  cc   = is_k ? c : (c - 128);
    const int  h    = cc & 3;
    const int  g    = cc >> 2;
    // segments: 0=khi 1=klo 2=vhi 3=vlo (x4 h each)
    __nv_bfloat16* shi = stage + ((is_k ? 0 : 8) + h) * STG_PITCH + g;
    __nv_bfloat16* slo = shi + 4 * STG_PITCH;

#pragma unroll
    for (int r = 0; r < 32; r++) {
        float val = acc[r];
        if (is_k) {
            float ss = val * val;
            ss += __shfl_xor_sync(0xffffffffu, ss, 1);
            ss += __shfl_xor_sync(0xffffffffu, ss, 2);
            val = val / fmaxf(sqrtf(ss), 1e-12f) * 10.f;
        }
        __nv_bfloat16 hi = __float2bfloat16_rn(val);
        __nv_bfloat16 lo = __float2bfloat16_rn(val - __bfloat162float(hi));
        shi[r * 32] = hi;
        slo[r * 32] = lo;
    }
    __syncthreads();

    // coalesced copy-out: 16 segments x 1024 bf16 = 128 uint4 each
    const int b   = row0 >> 12;
    const int dh  = (row0 & 4095) >> 7;
    const int ib  = (row0 & 127) * 32;
    __nv_bfloat16* const arr[4] = {g_KThi, g_KTlo, g_VThi, g_VTlo};
    for (int idx = tid; idx < 16 * 128; idx += 256) {
        int seg = idx >> 7, t = idx & 127;
        int a = seg >> 2, hh = seg & 3;
        uint4 v = ((const uint4*)stage)[seg * (STG_PITCH / 8) + t];
        __nv_bfloat16* dst = arr[a] + ((size_t)((b * 4 + hh) * DH + dh)) * SEQ + ib;
        ((uint4*)dst)[t] = v;
    }
}

// ---------------------------------------------------------------------------
// Kernel 2: flash attention. 128 thr (4 warps), M=64 tile, j-tiles of 128
// processed as two n64 halves. All operands via ldmatrix from transposed
// [dh][seq] tiles; hi/lo error-compensated bf16 HMMA.
// ---------------------------------------------------------------------------
#define KT_PITCH 72
#define VT_PITCH 136
#define KT_ELEMS (64 * KT_PITCH)             // 4608
#define VT_ELEMS (DH * VT_PITCH)             // 4352 per tensor per stage
#define ATTN_SMEM ((KT_ELEMS + 2 * 2 * VT_ELEMS) * 2)   // 44032 bytes

__global__ __launch_bounds__(128, 3) void attn_kernel() {
    extern __shared__ __nv_bfloat16 sm[];
    __nv_bfloat16* KTs = sm;                    // [64][72]: rows 0-31 Khi, 32-63 Klo
    __nv_bfloat16* VTs = sm + KT_ELEMS;         // [2 stages][2 hi/lo][32][136]

    const int p  = blockIdx.y;
    const int i0 = blockIdx.x * 64;
    const int tid  = threadIdx.x;
    const int wid  = tid >> 5;
    const int lane = tid & 31;
    const int mrow = wid * 16;

    const __nv_bfloat16* KTh = g_KThi + (size_t)p * DH * SEQ;
    const __nv_bfloat16* KTl = g_KTlo + (size_t)p * DH * SEQ;
    const __nv_bfloat16* VTh = g_VThi + (size_t)p * DH * SEQ;
    const __nv_bfloat16* VTl = g_VTlo + (size_t)p * DH * SEQ;

    auto prefetch = [&](int s, int j0) {
        for (int t = tid; t < 1024; t += 128) {
            int which = t >> 9;
            int rem = t & 511;
            int d = rem >> 4, q = rem & 15;
            const __nv_bfloat16* src = (which ? VTl : VTh) + (size_t)d * SEQ + j0 + q * 8;
            cp16(VTs + (s * 2 + which) * VT_ELEMS + d * VT_PITCH + q * 8, src);
        }
    };

    // stage 0 + KT tile, then stage 1
    prefetch(0, 0);
    for (int t = tid; t < 512; t += 128) {
        int row = t >> 3, q = t & 7;
        const __nv_bfloat16* src = (row < 32 ? KTh : KTl) + (size_t)(row & 31) * SEQ + i0 + q * 8;
        cp16(KTs + row * KT_PITCH + q * 8, src);
    }
    asm volatile("cp.async.commit_group;");
    prefetch(1, 128);
    asm volatile("cp.async.commit_group;");
    asm volatile("cp.async.wait_group 1;");
    __syncthreads();

    // A fragments (constant over j loop): Khi, Klo k=32 each (2 chunks of k16)
    const int grp = lane >> 3, l8 = lane & 7;
    uint ahi[2][4], alo[2][4];
    {
        int ar  = (grp >> 1) * 8 + l8;          // k sub-row
        int acl = mrow + (grp & 1) * 8;         // m col
#pragma unroll
        for (int kt = 0; kt < 2; kt++) {
            ldsm4t(ahi[kt], KTs + (kt * 16 + ar) * KT_PITCH + acl);
            ldsm4t(alo[kt], KTs + (32 + kt * 16 + ar) * KT_PITCH + acl);
        }
    }

    float m[2] = {-1e30f, -1e30f}, l[2] = {0.f, 0.f};
    float acc[4][4];
#pragma unroll
    for (int nt = 0; nt < 4; nt++)
#pragma unroll
        for (int e = 0; e < 4; e++) acc[nt][e] = 0.f;

    const int bkr = (grp & 1) * 8 + l8;     // S-B: k sub-row
    const int bnc = (grp >> 1) * 8;         // S-B: n col offset
    const int pnr = (grp >> 1) * 8 + l8;    // PV-B: n sub-row
    const int pkc = (grp & 1) * 8;          // PV-B: k col offset

    for (int it = 0; it < 32; it++) {
        const __nv_bfloat16* Vh = VTs + ((it & 1) * 2) * VT_ELEMS;
        const __nv_bfloat16* Vl = Vh + VT_ELEMS;

#pragma unroll
        for (int half = 0; half < 2; half++) {
            const int jh = half * 64;
            float S[8][4];
#pragma unroll
            for (int jt = 0; jt < 8; jt++)
#pragma unroll
                for (int e = 0; e < 4; e++) S[jt][e] = 0.f;

            // ---- S = Khi.Vhi + Khi.Vlo + Klo.Vhi ----
#pragma unroll
            for (int g = 0; g < 4; g++) {
                const int n0 = jh + g * 16 + bnc;
                uint bh0[4], bh1[4], bl0[4], bl1[4];
                ldsm4t(bh0, Vh + (bkr)      * VT_PITCH + n0);
                ldsm4t(bh1, Vh + (16 + bkr) * VT_PITCH + n0);
                ldsm4t(bl0, Vl + (bkr)      * VT_PITCH + n0);
                ldsm4t(bl1, Vl + (16 + bkr) * VT_PITCH + n0);
                float* s0 = S[2 * g];
                float* s1 = S[2 * g + 1];
                mma16816(s0, ahi[0], bh0[0], bh0[1]); mma16816(s0, ahi[1], bh1[0], bh1[1]);
                mma16816(s0, ahi[0], bl0[0], bl0[1]); mma16816(s0, ahi[1], bl1[0], bl1[1]);
                mma16816(s0, alo[0], bh0[0], bh0[1]); mma16816(s0, alo[1], bh1[0], bh1[1]);
                mma16816(s1, ahi[0], bh0[2], bh0[3]); mma16816(s1, ahi[1], bh1[2], bh1[3]);
                mma16816(s1, ahi[0], bl0[2], bl0[3]); mma16816(s1, ahi[1], bl1[2], bl1[3]);
                mma16816(s1, alo[0], bh0[2], bh0[3]); mma16816(s1, alo[1], bh1[2], bh1[3]);
            }

            // ---- online softmax (rows lane/4 and +8) ----
#pragma unroll
            for (int r = 0; r < 2; r++) {
                float mx = -1e30f;
#pragma unroll
                for (int jt = 0; jt < 8; jt++)
                    mx = fmaxf(mx, fmaxf(S[jt][2 * r], S[jt][2 * r + 1]));
                mx = fmaxf(mx, __shfl_xor_sync(0xffffffffu, mx, 1));
                mx = fmaxf(mx, __shfl_xor_sync(0xffffffffu, mx, 2));
                float mnew  = fmaxf(m[r], mx);
                float alpha = __expf(m[r] - mnew);
                m[r] = mnew;
                float rs = 0.f;
#pragma unroll
                for (int jt = 0; jt < 8; jt++) {
                    float e0 = __expf(S[jt][2 * r] - mnew);
                    float e1 = __expf(S[jt][2 * r + 1] - mnew);
                    S[jt][2 * r] = e0; S[jt][2 * r + 1] = e1;
                    rs += e0 + e1;
                }
                rs += __shfl_xor_sync(0xffffffffu, rs, 1);
                rs += __shfl_xor_sync(0xffffffffu, rs, 2);
                l[r] = l[r] * alpha + rs;
#pragma unroll
                for (int nt = 0; nt < 4; nt++) {
                    acc[nt][2 * r]     *= alpha;
                    acc[nt][2 * r + 1] *= alpha;
                }
            }

            // ---- PV: acc += Phi.Vhi + Phi.Vlo + Plo.Vhi ----
#pragma unroll
            for (int cch = 0; cch < 4; cch++) {
                float* t0 = S[2 * cch];
                float* t1 = S[2 * cch + 1];
                uint ah[4], al[4];
                ah[0] = packbf(t0[0], t0[1]);  al[0] = packlo(t0[0], t0[1], ah[0]);
                ah[1] = packbf(t0[2], t0[3]);  al[1] = packlo(t0[2], t0[3], ah[1]);
                ah[2] = packbf(t1[0], t1[1]);  al[2] = packlo(t1[0], t1[1], ah[2]);
                ah[3] = packbf(t1[2], t1[3]);  al[3] = packlo(t1[2], t1[3], ah[3]);
                const int k0 = jh + cch * 16 + pkc;
#pragma unroll
                for (int q = 0; q < 2; q++) {
                    uint rh[4], rl[4];
                    ldsm4(rh, Vh + (q * 16 + pnr) * VT_PITCH + k0);
                    ldsm4(rl, Vl + (q * 16 + pnr) * VT_PITCH + k0);
                    float* a0 = acc[2 * q];
                    float* a1 = acc[2 * q + 1];
                    mma16816(a0, ah, rh[0], rh[1]);
                    mma16816(a0, ah, rl[0], rl[1]);
                    mma16816(a0, al, rh[0], rh[1]);
                    mma16816(a1, ah, rh[2], rh[3]);
                    mma16816(a1, ah, rl[2], rl[3]);
                    mma16816(a1, al, rh[2], rh[3]);
                }
            }
        }

        __syncthreads();   // all warps done with stage it&1
        if (it + 2 < 32) prefetch((it + 2) & 1, (it + 2) * 128);
        asm volatile("cp.async.commit_group;");
        asm volatile("cp.async.wait_group 1;");
        __syncthreads();   // stage (it+1)&1 ready
    }

    // ---- epilogue ----
    const int b = p >> 2, h = p & 3;
    int row0 = i0 + mrow + (lane >> 2);
    int row1 = row0 + 8;
    float inv0 = 1.f / l[0], inv1 = 1.f / l[1];
#pragma unroll
    for (int nt = 0; nt < 4; nt++) {
#pragma unroll
        for (int e = 0; e < 2; e++) {
            int dh = nt * 8 + (lane & 3) * 2 + e;
            g_O[((size_t)b * SEQ + row0) * 128 + dh * 4 + h] = acc[nt][e] * inv0;
            g_O[((size_t)b * SEQ + row1) * 128 + dh * 4 + h] = acc[nt][2 + e] * inv1;
        }
    }
}

// ---------------------------------------------------------------------------
// Kernel 3: y = O @ w_out + b_out
// ---------------------------------------------------------------------------
__global__ __launch_bounds__(128) void proj_out_kernel(const float* __restrict__ w_out,
                                                       const float* __restrict__ b_out,
                                                       float* __restrict__ y) {
    __shared__ float osh[128][36];
    const int row0 = blockIdx.x * 32;
    const int tid  = threadIdx.x;

    for (int idx = tid; idx < 32 * 128; idx += 128) {
        int r = idx >> 7, k = idx & 127;
        osh[k][r] = g_O[(row0 + r) * 128 + k];
    }
    __syncthreads();

    const int c = tid;
    float acc[32];
#pragma unroll
    for (int r = 0; r < 32; r++) acc[r] = 0.f;

    for (int k0 = 0; k0 < 128; k0 += 8) {
        float wr[8];
#pragma unroll
        for (int u = 0; u < 8; u++) wr[u] = w_out[(k0 + u) * 128 + c];
#pragma unroll
        for (int u = 0; u < 8; u++) {
            int k = k0 + u;
#pragma unroll
            for (int r4 = 0; r4 < 8; r4++) {
                float4 a = *(const float4*)&osh[k][r4 * 4];
                acc[r4 * 4 + 0] += a.x * wr[u];
                acc[r4 * 4 + 1] += a.y * wr[u];
                acc[r4 * 4 + 2] += a.z * wr[u];
                acc[r4 * 4 + 3] += a.w * wr[u];
            }
        }
    }
    float bias = b_out[c];
#pragma unroll
    for (int r = 0; r < 32; r++)
        y[(row0 + r) * 128 + c] = acc[r] + bias;
}

// ---------------------------------------------------------------------------
extern "C" void kernel_launch(void* const* d_in, const int* in_sizes, int n_in,
                              void* d_out, int out_size) {
    const float *x = nullptr, *wq = nullptr, *wo = nullptr, *bo = nullptr;
    for (int idx = 0; idx < n_in; idx++) {
        switch (in_sizes[idx]) {
            case 4 * 16 * 256 * 128: x  = (const float*)d_in[idx]; break;
            case 128 * 384:          wq = (const float*)d_in[idx]; break;
            case 128 * 128:          wo = (const float*)d_in[idx]; break;
            case 128:                bo = (const float*)d_in[idx]; break;
        }
    }
    float* y = (float*)d_out;

    cudaFuncSetAttribute(attn_kernel, cudaFuncAttributeMaxDynamicSharedMemorySize, ATTN_SMEM);
    cudaFuncSetAttribute(proj_kv_kernel, cudaFuncAttributeMaxDynamicSharedMemorySize, PROJ_SMEM);

    proj_kv_kernel<<<512, 256, PROJ_SMEM>>>(x, wq);
    attn_kernel<<<dim3(64, NPAIR), 128, ATTN_SMEM>>>();
    proj_out_kernel<<<512, 128>>>(wo, bo, y);
}

// round 9
// speedup vs baseline: 3.8887x; 1.5504x over previous
#include <cuda_runtime.h>
#include <cuda_bf16.h>

typedef unsigned int uint;

#define SEQ   4096
#define DH    32
#define NPAIR 16

// ---------------------------------------------------------------------------
// Device scratch — all transposed layouts [pair][dh][SEQ] for coalesced stores
// ---------------------------------------------------------------------------
__device__ __nv_bfloat16 g_KThi[NPAIR * DH * SEQ];
__device__ __nv_bfloat16 g_KTlo[NPAIR * DH * SEQ];
__device__ __nv_bfloat16 g_VThi[NPAIR * DH * SEQ];
__device__ __nv_bfloat16 g_VTlo[NPAIR * DH * SEQ];
__device__ float g_O[4 * SEQ * 128];

// ---------------------------------------------------------------------------
// PTX helpers
// ---------------------------------------------------------------------------
__device__ __forceinline__ void cp16(void* dst, const void* src) {
    unsigned d = (unsigned)__cvta_generic_to_shared(dst);
    asm volatile("cp.async.cg.shared.global [%0], [%1], 16;" :: "r"(d), "l"(src));
}
__device__ __forceinline__ void ldsm4(uint* r, const void* p) {
    unsigned a = (unsigned)__cvta_generic_to_shared(p);
    asm volatile("ldmatrix.sync.aligned.m8n8.x4.shared.b16 {%0,%1,%2,%3}, [%4];"
                 : "=r"(r[0]), "=r"(r[1]), "=r"(r[2]), "=r"(r[3]) : "r"(a));
}
__device__ __forceinline__ void ldsm4t(uint* r, const void* p) {
    unsigned a = (unsigned)__cvta_generic_to_shared(p);
    asm volatile("ldmatrix.sync.aligned.m8n8.x4.trans.shared.b16 {%0,%1,%2,%3}, [%4];"
                 : "=r"(r[0]), "=r"(r[1]), "=r"(r[2]), "=r"(r[3]) : "r"(a));
}
__device__ __forceinline__ void mma16816(float* c, const uint* a, uint b0, uint b1) {
    asm volatile("mma.sync.aligned.m16n8k16.row.col.f32.bf16.bf16.f32 "
                 "{%0,%1,%2,%3},{%4,%5,%6,%7},{%8,%9},{%0,%1,%2,%3};"
                 : "+f"(c[0]), "+f"(c[1]), "+f"(c[2]), "+f"(c[3])
                 : "r"(a[0]), "r"(a[1]), "r"(a[2]), "r"(a[3]), "r"(b0), "r"(b1));
}
__device__ __forceinline__ uint packbf(float x, float y) {
    __nv_bfloat162 t = __floats2bfloat162_rn(x, y);
    return *(uint*)&t;
}
__device__ __forceinline__ uint packlo(float x, float y, uint hi) {
    __nv_bfloat162 h = *(__nv_bfloat162*)&hi;
    return packbf(x - __bfloat162float(h.x), y - __bfloat162float(h.y));
}

// ---------------------------------------------------------------------------
// Kernel 1: kv projection + l2 norm + hi/lo split; smem-staged coalesced stores
// Block: 32 rows (one b, one dh page), 256 threads (128 K-ch, 128 V-ch)
// ---------------------------------------------------------------------------
#define STG_PITCH 1040                       // 1024 + 16 pad (elements)
#define PROJ_SMEM (16 * STG_PITCH * 2)       // 33280 bytes (also covers xsh 18432)

__global__ __launch_bounds__(256) void proj_kv_kernel(const float* __restrict__ x,
                                                      const float* __restrict__ w_qkv) {
    extern __shared__ char psm[];
    float* xsh = (float*)psm;                          // [128][36]
    __nv_bfloat16* stage = (__nv_bfloat16*)psm;        // [16][1040] (reused after compute)

    const int row0 = blockIdx.x * 32;
    const int tid  = threadIdx.x;

    for (int idx = tid; idx < 32 * 128; idx += 256) {
        int r = idx >> 7, k = idx & 127;
        xsh[k * 36 + r] = x[(row0 + r) * 128 + k];
    }
    __syncthreads();

    const int c = tid;
    float acc[32];
#pragma unroll
    for (int r = 0; r < 32; r++) acc[r] = 0.f;

    const float* wp = w_qkv + 128 + c;
    for (int k0 = 0; k0 < 128; k0 += 8) {
        float wr[8];
#pragma unroll
        for (int u = 0; u < 8; u++) wr[u] = wp[(k0 + u) * 384];
#pragma unroll
        for (int u = 0; u < 8; u++) {
            const float* xr = xsh + (k0 + u) * 36;
#pragma unroll
            for (int r4 = 0; r4 < 8; r4++) {
                float4 a = *(const float4*)&xr[r4 * 4];
                acc[r4 * 4 + 0] += a.x * wr[u];
                acc[r4 * 4 + 1] += a.y * wr[u];
                acc[r4 * 4 + 2] += a.z * wr[u];
                acc[r4 * 4 + 3] += a.w * wr[u];
            }
        }
    }
    __syncthreads();   // done reading xsh; reuse as staging

    const bool is_k = (c < 128);
    const int  cc   = is_k ? c : (c - 128);
    const int  h    = cc & 3;
    const int  g    = cc >> 2;
    // segments: 0=khi 1=klo 2=vhi 3=vlo (x4 h each)
    __nv_bfloat16* shi = stage + ((is_k ? 0 : 8) + h) * STG_PITCH + g;
    __nv_bfloat16* slo = shi + 4 * STG_PITCH;

#pragma unroll
    for (int r = 0; r < 32; r++) {
        float val = acc[r];
        if (is_k) {
            float ss = val * val;
            ss += __shfl_xor_sync(0xffffffffu, ss, 1);
            ss += __shfl_xor_sync(0xffffffffu, ss, 2);
            val = val / fmaxf(sqrtf(ss), 1e-12f) * 10.f;
        }
        __nv_bfloat16 hi = __float2bfloat16_rn(val);
        __nv_bfloat16 lo = __float2bfloat16_rn(val - __bfloat162float(hi));
        shi[r * 32] = hi;
        slo[r * 32] = lo;
    }
    __syncthreads();

    // coalesced copy-out: 16 segments x 1024 bf16 = 128 uint4 each
    const int b   = row0 >> 12;
    const int dh  = (row0 & 4095) >> 7;
    const int ib  = (row0 & 127) * 32;
    __nv_bfloat16* const arr[4] = {g_KThi, g_KTlo, g_VThi, g_VTlo};
    for (int idx = tid; idx < 16 * 128; idx += 256) {
        int seg = idx >> 7, t = idx & 127;
        int a = seg >> 2, hh = seg & 3;
        uint4 v = ((const uint4*)stage)[seg * (STG_PITCH / 8) + t];
        __nv_bfloat16* dst = arr[a] + ((size_t)((b * 4 + hh) * DH + dh)) * SEQ + ib;
        ((uint4*)dst)[t] = v;
    }
}

// ---------------------------------------------------------------------------
// Kernel 2: flash attention. 128 thr (4 warps), M=64 tile, j-tiles of 128
// processed as two n64 halves. All operands via ldmatrix from transposed
// [dh][seq] tiles; hi/lo error-compensated bf16 HMMA.
// ---------------------------------------------------------------------------
#define KT_PITCH 72
#define VT_PITCH 136
#define KT_ELEMS (64 * KT_PITCH)             // 4608
#define VT_ELEMS (DH * VT_PITCH)             // 4352 per tensor per stage
#define ATTN_SMEM ((KT_ELEMS + 2 * 2 * VT_ELEMS) * 2)   // 44032 bytes

__global__ __launch_bounds__(128, 3) void attn_kernel() {
    extern __shared__ __nv_bfloat16 sm[];
    __nv_bfloat16* KTs = sm;                    // [64][72]: rows 0-31 Khi, 32-63 Klo
    __nv_bfloat16* VTs = sm + KT_ELEMS;         // [2 stages][2 hi/lo][32][136]

    const int p  = blockIdx.y;
    const int i0 = blockIdx.x * 64;
    const int tid  = threadIdx.x;
    const int wid  = tid >> 5;
    const int lane = tid & 31;
    const int mrow = wid * 16;

    const __nv_bfloat16* KTh = g_KThi + (size_t)p * DH * SEQ;
    const __nv_bfloat16* KTl = g_KTlo + (size_t)p * DH * SEQ;
    const __nv_bfloat16* VTh = g_VThi + (size_t)p * DH * SEQ;
    const __nv_bfloat16* VTl = g_VTlo + (size_t)p * DH * SEQ;

    auto prefetch = [&](int s, int j0) {
        for (int t = tid; t < 1024; t += 128) {
            int which = t >> 9;
            int rem = t & 511;
            int d = rem >> 4, q = rem & 15;
            const __nv_bfloat16* src = (which ? VTl : VTh) + (size_t)d * SEQ + j0 + q * 8;
            cp16(VTs + (s * 2 + which) * VT_ELEMS + d * VT_PITCH + q * 8, src);
        }
    };

    // stage 0 + KT tile, then stage 1
    prefetch(0, 0);
    for (int t = tid; t < 512; t += 128) {
        int row = t >> 3, q = t & 7;
        const __nv_bfloat16* src = (row < 32 ? KTh : KTl) + (size_t)(row & 31) * SEQ + i0 + q * 8;
        cp16(KTs + row * KT_PITCH + q * 8, src);
    }
    asm volatile("cp.async.commit_group;");
    prefetch(1, 128);
    asm volatile("cp.async.commit_group;");
    asm volatile("cp.async.wait_group 1;");
    __syncthreads();

    // A fragments (constant over j loop): Khi, Klo k=32 each (2 chunks of k16)
    const int grp = lane >> 3, l8 = lane & 7;
    uint ahi[2][4], alo[2][4];
    {
        int ar  = (grp >> 1) * 8 + l8;          // k sub-row
        int acl = mrow + (grp & 1) * 8;         // m col
#pragma unroll
        for (int kt = 0; kt < 2; kt++) {
            ldsm4t(ahi[kt], KTs + (kt * 16 + ar) * KT_PITCH + acl);
            ldsm4t(alo[kt], KTs + (32 + kt * 16 + ar) * KT_PITCH + acl);
        }
    }

    float m[2] = {-1e30f, -1e30f}, l[2] = {0.f, 0.f};
    float acc[4][4];
#pragma unroll
    for (int nt = 0; nt < 4; nt++)
#pragma unroll
        for (int e = 0; e < 4; e++) acc[nt][e] = 0.f;

    const int bkr = (grp & 1) * 8 + l8;     // S-B: k sub-row
    const int bnc = (grp >> 1) * 8;         // S-B: n col offset
    const int pnr = (grp >> 1) * 8 + l8;    // PV-B: n sub-row
    const int pkc = (grp & 1) * 8;          // PV-B: k col offset

    for (int it = 0; it < 32; it++) {
        const __nv_bfloat16* Vh = VTs + ((it & 1) * 2) * VT_ELEMS;
        const __nv_bfloat16* Vl = Vh + VT_ELEMS;

#pragma unroll
        for (int half = 0; half < 2; half++) {
            const int jh = half * 64;
            float S[8][4];
#pragma unroll
            for (int jt = 0; jt < 8; jt++)
#pragma unroll
                for (int e = 0; e < 4; e++) S[jt][e] = 0.f;

            // ---- S = Khi.Vhi + Khi.Vlo + Klo.Vhi ----
#pragma unroll
            for (int g = 0; g < 4; g++) {
                const int n0 = jh + g * 16 + bnc;
                uint bh0[4], bh1[4], bl0[4], bl1[4];
                ldsm4t(bh0, Vh + (bkr)      * VT_PITCH + n0);
                ldsm4t(bh1, Vh + (16 + bkr) * VT_PITCH + n0);
                ldsm4t(bl0, Vl + (bkr)      * VT_PITCH + n0);
                ldsm4t(bl1, Vl + (16 + bkr) * VT_PITCH + n0);
                float* s0 = S[2 * g];
                float* s1 = S[2 * g + 1];
                mma16816(s0, ahi[0], bh0[0], bh0[1]); mma16816(s0, ahi[1], bh1[0], bh1[1]);
                mma16816(s0, ahi[0], bl0[0], bl0[1]); mma16816(s0, ahi[1], bl1[0], bl1[1]);
                mma16816(s0, alo[0], bh0[0], bh0[1]); mma16816(s0, alo[1], bh1[0], bh1[1]);
                mma16816(s1, ahi[0], bh0[2], bh0[3]); mma16816(s1, ahi[1], bh1[2], bh1[3]);
                mma16816(s1, ahi[0], bl0[2], bl0[3]); mma16816(s1, ahi[1], bl1[2], bl1[3]);
                mma16816(s1, alo[0], bh0[2], bh0[3]); mma16816(s1, alo[1], bh1[2], bh1[3]);
            }

            // ---- online softmax (rows lane/4 and +8) ----
#pragma unroll
            for (int r = 0; r < 2; r++) {
                float mx = -1e30f;
#pragma unroll
                for (int jt = 0; jt < 8; jt++)
                    mx = fmaxf(mx, fmaxf(S[jt][2 * r], S[jt][2 * r + 1]));
                mx = fmaxf(mx, __shfl_xor_sync(0xffffffffu, mx, 1));
                mx = fmaxf(mx, __shfl_xor_sync(0xffffffffu, mx, 2));
                float mnew  = fmaxf(m[r], mx);
                float alpha = __expf(m[r] - mnew);
                m[r] = mnew;
                float rs = 0.f;
#pragma unroll
                for (int jt = 0; jt < 8; jt++) {
                    float e0 = __expf(S[jt][2 * r] - mnew);
                    float e1 = __expf(S[jt][2 * r + 1] - mnew);
                    S[jt][2 * r] = e0; S[jt][2 * r + 1] = e1;
                    rs += e0 + e1;
                }
                rs += __shfl_xor_sync(0xffffffffu, rs, 1);
                rs += __shfl_xor_sync(0xffffffffu, rs, 2);
                l[r] = l[r] * alpha + rs;
#pragma unroll
                for (int nt = 0; nt < 4; nt++) {
                    acc[nt][2 * r]     *= alpha;
                    acc[nt][2 * r + 1] *= alpha;
                }
            }

            // ---- PV: acc += Phi.Vhi + Phi.Vlo + Plo.Vhi ----
#pragma unroll
            for (int cch = 0; cch < 4; cch++) {
                float* t0 = S[2 * cch];
                float* t1 = S[2 * cch + 1];
                uint ah[4], al[4];
                ah[0] = packbf(t0[0], t0[1]);  al[0] = packlo(t0[0], t0[1], ah[0]);
                ah[1] = packbf(t0[2], t0[3]);  al[1] = packlo(t0[2], t0[3], ah[1]);
                ah[2] = packbf(t1[0], t1[1]);  al[2] = packlo(t1[0], t1[1], ah[2]);
                ah[3] = packbf(t1[2], t1[3]);  al[3] = packlo(t1[2], t1[3], ah[3]);
                const int k0 = jh + cch * 16 + pkc;
#pragma unroll
                for (int q = 0; q < 2; q++) {
                    uint rh[4], rl[4];
                    ldsm4(rh, Vh + (q * 16 + pnr) * VT_PITCH + k0);
                    ldsm4(rl, Vl + (q * 16 + pnr) * VT_PITCH + k0);
                    float* a0 = acc[2 * q];
                    float* a1 = acc[2 * q + 1];
                    mma16816(a0, ah, rh[0], rh[1]);
                    mma16816(a0, ah, rl[0], rl[1]);
                    mma16816(a0, al, rh[0], rh[1]);
                    mma16816(a1, ah, rh[2], rh[3]);
                    mma16816(a1, ah, rl[2], rl[3]);
                    mma16816(a1, al, rh[2], rh[3]);
                }
            }
        }

        __syncthreads();   // all warps done with stage it&1
        if (it + 2 < 32) prefetch((it + 2) & 1, (it + 2) * 128);
        asm volatile("cp.async.commit_group;");
        asm volatile("cp.async.wait_group 1;");
        __syncthreads();   // stage (it+1)&1 ready
    }

    // ---- epilogue ----
    const int b = p >> 2, h = p & 3;
    int row0 = i0 + mrow + (lane >> 2);
    int row1 = row0 + 8;
    float inv0 = 1.f / l[0], inv1 = 1.f / l[1];
#pragma unroll
    for (int nt = 0; nt < 4; nt++) {
#pragma unroll
        for (int e = 0; e < 2; e++) {
            int dh = nt * 8 + (lane & 3) * 2 + e;
            g_O[((size_t)b * SEQ + row0) * 128 + dh * 4 + h] = acc[nt][e] * inv0;
            g_O[((size_t)b * SEQ + row1) * 128 + dh * 4 + h] = acc[nt][2 + e] * inv1;
        }
    }
}

// ---------------------------------------------------------------------------
// Kernel 3: y = O @ w_out + b_out
// ---------------------------------------------------------------------------
__global__ __launch_bounds__(128) void proj_out_kernel(const float* __restrict__ w_out,
                                                       const float* __restrict__ b_out,
                                                       float* __restrict__ y) {
    __shared__ float osh[128][36];
    const int row0 = blockIdx.x * 32;
    const int tid  = threadIdx.x;

    for (int idx = tid; idx < 32 * 128; idx += 128) {
        int r = idx >> 7, k = idx & 127;
        osh[k][r] = g_O[(row0 + r) * 128 + k];
    }
    __syncthreads();

    const int c = tid;
    float acc[32];
#pragma unroll
    for (int r = 0; r < 32; r++) acc[r] = 0.f;

    for (int k0 = 0; k0 < 128; k0 += 8) {
        float wr[8];
#pragma unroll
        for (int u = 0; u < 8; u++) wr[u] = w_out[(k0 + u) * 128 + c];
#pragma unroll
        for (int u = 0; u < 8; u++) {
            int k = k0 + u;
#pragma unroll
            for (int r4 = 0; r4 < 8; r4++) {
                float4 a = *(const float4*)&osh[k][r4 * 4];
                acc[r4 * 4 + 0] += a.x * wr[u];
                acc[r4 * 4 + 1] += a.y * wr[u];
                acc[r4 * 4 + 2] += a.z * wr[u];
                acc[r4 * 4 + 3] += a.w * wr[u];
            }
        }
    }
    float bias = b_out[c];
#pragma unroll
    for (int r = 0; r < 32; r++)
        y[(row0 + r) * 128 + c] = acc[r] + bias;
}

// ---------------------------------------------------------------------------
extern "C" void kernel_launch(void* const* d_in, const int* in_sizes, int n_in,
                              void* d_out, int out_size) {
    const float *x = nullptr, *wq = nullptr, *wo = nullptr, *bo = nullptr;
    for (int idx = 0; idx < n_in; idx++) {
        switch (in_sizes[idx]) {
            case 4 * 16 * 256 * 128: x  = (const float*)d_in[idx]; break;
            case 128 * 384:          wq = (const float*)d_in[idx]; break;
            case 128 * 128:          wo = (const float*)d_in[idx]; break;
            case 128:                bo = (const float*)d_in[idx]; break;
        }
    }
    float* y = (float*)d_out;

    cudaFuncSetAttribute(attn_kernel, cudaFuncAttributeMaxDynamicSharedMemorySize, ATTN_SMEM);
    cudaFuncSetAttribute(proj_kv_kernel, cudaFuncAttributeMaxDynamicSharedMemorySize, PROJ_SMEM);

    proj_kv_kernel<<<512, 256, PROJ_SMEM>>>(x, wq);
    attn_kernel<<<dim3(64, NPAIR), 128, ATTN_SMEM>>>();
    proj_out_kernel<<<512, 128>>>(wo, bo, y);
}

// round 15
// speedup vs baseline: 4.3190x; 1.1107x over previous
#include <cuda_runtime.h>
#include <cuda_bf16.h>

typedef unsigned int uint;

#define SEQ   4096
#define DH    32
#define NPAIR 16

// ---------------------------------------------------------------------------
// Device scratch
// ---------------------------------------------------------------------------
__device__ __nv_bfloat16 g_KThi[NPAIR * DH * SEQ];
__device__ __nv_bfloat16 g_KTlo[NPAIR * DH * SEQ];
__device__ __nv_bfloat16 g_VThi[NPAIR * DH * SEQ];
__device__ __nv_bfloat16 g_VTlo[NPAIR * DH * SEQ];
__device__ float g_O[4 * SEQ * 128];
// pre-split weights (hi/lo bf16), built once by prep_w_kernel
__device__ __nv_bfloat16 g_Whi[128 * 256];    // w_qkv cols 128..383 -> [k][n]
__device__ __nv_bfloat16 g_Wlo[128 * 256];
__device__ __nv_bfloat16 g_WOhi[128 * 128];   // w_out [k][n]
__device__ __nv_bfloat16 g_WOlo[128 * 128];

// ---------------------------------------------------------------------------
// PTX helpers
// ---------------------------------------------------------------------------
__device__ __forceinline__ void cp16(void* dst, const void* src) {
    unsigned d = (unsigned)__cvta_generic_to_shared(dst);
    asm volatile("cp.async.cg.shared.global [%0], [%1], 16;" :: "r"(d), "l"(src));
}
__device__ __forceinline__ void ldsm4(uint* r, const void* p) {
    unsigned a = (unsigned)__cvta_generic_to_shared(p);
    asm volatile("ldmatrix.sync.aligned.m8n8.x4.shared.b16 {%0,%1,%2,%3}, [%4];"
                 : "=r"(r[0]), "=r"(r[1]), "=r"(r[2]), "=r"(r[3]) : "r"(a));
}
__device__ __forceinline__ void ldsm4t(uint* r, const void* p) {
    unsigned a = (unsigned)__cvta_generic_to_shared(p);
    asm volatile("ldmatrix.sync.aligned.m8n8.x4.trans.shared.b16 {%0,%1,%2,%3}, [%4];"
                 : "=r"(r[0]), "=r"(r[1]), "=r"(r[2]), "=r"(r[3]) : "r"(a));
}
__device__ __forceinline__ void mma16816(float* c, const uint* a, uint b0, uint b1) {
    asm volatile("mma.sync.aligned.m16n8k16.row.col.f32.bf16.bf16.f32 "
                 "{%0,%1,%2,%3},{%4,%5,%6,%7},{%8,%9},{%0,%1,%2,%3};"
                 : "+f"(c[0]), "+f"(c[1]), "+f"(c[2]), "+f"(c[3])
                 : "r"(a[0]), "r"(a[1]), "r"(a[2]), "r"(a[3]), "r"(b0), "r"(b1));
}
__device__ __forceinline__ uint packbf(float x, float y) {
    __nv_bfloat162 t = __floats2bfloat162_rn(x, y);
    return *(uint*)&t;
}
__device__ __forceinline__ uint packlo(float x, float y, uint hi) {
    __nv_bfloat162 h = *(__nv_bfloat162*)&hi;
    return packbf(x - __bfloat162float(h.x), y - __bfloat162float(h.y));
}

// ---------------------------------------------------------------------------
// Kernel 0: split weights into bf16 hi/lo
// ---------------------------------------------------------------------------
__global__ __launch_bounds__(256) void prep_w_kernel(const float* __restrict__ w_qkv,
                                                     const float* __restrict__ w_out) {
    int t0 = blockIdx.x * 256 + threadIdx.x;
    for (int i = t0; i < 128 * 256; i += gridDim.x * 256) {
        int k = i >> 8, n = i & 255;
        float v = w_qkv[k * 384 + 128 + n];
        __nv_bfloat16 hi = __float2bfloat16_rn(v);
        g_Whi[i] = hi;
        g_Wlo[i] = __float2bfloat16_rn(v - __bfloat162float(hi));
    }
    for (int i = t0; i < 128 * 128; i += gridDim.x * 256) {
        float v = w_out[i];
        __nv_bfloat16 hi = __float2bfloat16_rn(v);
        g_WOhi[i] = hi;
        g_WOlo[i] = __float2bfloat16_rn(v - __bfloat162float(hi));
    }
}

// ---------------------------------------------------------------------------
// Kernel 1: kv projection via 3-term bf16 HMMA + l2 norm + hi/lo split + scatter
// grid 128 (m-tiles of 128 rows = one (b,dh) page), 256 thr = 8 warps (m16 each)
// n processed in 4 chunks of 64 (chunks 0,1 = K channels; 2,3 = V channels)
// ---------------------------------------------------------------------------
#define XP 136
#define WP 72
#define PROJ_SMEM ((2 * 128 * XP + 2 * 128 * WP) * 2)   // 106496 B

__global__ __launch_bounds__(256, 1) void proj_kv_tc(const float* __restrict__ x) {
    extern __shared__ char sm[];
    __nv_bfloat16* Xhi = (__nv_bfloat16*)sm;        // [128][136]
    __nv_bfloat16* Xlo = Xhi + 128 * XP;
    __nv_bfloat16* Wh  = Xlo + 128 * XP;            // [128][72] per chunk
    __nv_bfloat16* Wl  = Wh + 128 * WP;

    const int row0 = blockIdx.x * 128;
    const int tid  = threadIdx.x;
    const int warp = tid >> 5;
    const int lane = tid & 31;
    const int mrow = warp * 16;
    const int grp  = lane >> 3, l8 = lane & 7;
    const int bkr  = (grp & 1) * 8 + l8;
    const int bnc  = (grp >> 1) * 8;

    // ---- load x tile, convert to bf16 hi/lo ----
    for (int idx = tid; idx < 128 * 32; idx += 256) {
        int r = idx >> 5, c4 = idx & 31;
        float4 v = *(const float4*)&x[(size_t)(row0 + r) * 128 + c4 * 4];
        uint h01 = packbf(v.x, v.y), h23 = packbf(v.z, v.w);
        uint l01 = packlo(v.x, v.y, h01), l23 = packlo(v.z, v.w, h23);
        *(uint2*)&Xhi[r * XP + c4 * 4] = make_uint2(h01, h23);
        *(uint2*)&Xlo[r * XP + c4 * 4] = make_uint2(l01, l23);
    }
    __syncthreads();

    const int bb = row0 >> 12;
    const int dh = (row0 & 4095) >> 7;

    for (int ch = 0; ch < 4; ch++) {
        const int n0 = ch * 64;
        // ---- load w chunk hi/lo ----
        for (int t = tid; t < 2048; t += 256) {
            int which = t >> 10;
            int rem = t & 1023;
            int k = rem >> 3, q = rem & 7;
            __nv_bfloat16* dst = (which ? Wl : Wh) + k * WP + q * 8;
            const __nv_bfloat16* src = (which ? g_Wlo : g_Whi) + k * 256 + n0 + q * 8;
            cp16(dst, src);
        }
        asm volatile("cp.async.commit_group;");
        asm volatile("cp.async.wait_group 0;");
        __syncthreads();

        // ---- 3-term GEMM: m16(warp) x n64 x k128 ----
        float acc[8][4];
#pragma unroll
        for (int t8 = 0; t8 < 8; t8++)
#pragma unroll
            for (int e = 0; e < 4; e++) acc[t8][e] = 0.f;

#pragma unroll
        for (int kc = 0; kc < 8; kc++) {
            uint ahi[4], alo[4];
            int aoff = (mrow + (lane & 15)) * XP + kc * 16 + 8 * (lane >> 4);
            ldsm4(ahi, Xhi + aoff);
            ldsm4(alo, Xlo + aoff);
#pragma unroll
            for (int g = 0; g < 4; g++) {
                uint bh[4], bl[4];
                int boff = (kc * 16 + bkr) * WP + g * 16 + bnc;
                ldsm4t(bh, Wh + boff);
                ldsm4t(bl, Wl + boff);
                float* s0 = acc[2 * g];
                float* s1 = acc[2 * g + 1];
                mma16816(s0, ahi, bh[0], bh[1]);
                mma16816(s0, ahi, bl[0], bl[1]);
                mma16816(s0, alo, bh[0], bh[1]);
                mma16816(s1, ahi, bh[2], bh[3]);
                mma16816(s1, ahi, bl[2], bl[3]);
                mma16816(s1, alo, bh[2], bh[3]);
            }
        }
        __syncthreads();   // all warps done reading Wh/Wl -> reuse as staging

        // ---- epilogue: (K only) 4-channel l2 norm, hi/lo split, stage ----
        const bool isK = (ch < 2);
        const int r0 = mrow + (lane >> 2);
        const int q  = lane & 3;
#pragma unroll
        for (int t8 = 0; t8 < 8; t8++) {
            const int c0  = t8 * 8 + q * 2;     // local n (even)
            const int h0  = c0 & 3;             // in {0,2}
            const int ggl = c0 >> 2;            // 0..15
#pragma unroll
            for (int rr = 0; rr < 2; rr++) {
                float v0 = acc[t8][rr * 2 + 0];
                float v1 = acc[t8][rr * 2 + 1];
                if (isK) {
                    float ss = v0 * v0 + v1 * v1;
                    ss += __shfl_xor_sync(0xffffffffu, ss, 1);
                    float inv = 10.f / fmaxf(sqrtf(ss), 1e-12f);
                    v0 *= inv; v1 *= inv;
                }
                int r = r0 + rr * 8;
                __nv_bfloat16 h_0 = __float2bfloat16_rn(v0);
                __nv_bfloat16 l_0 = __float2bfloat16_rn(v0 - __bfloat162float(h_0));
                __nv_bfloat16 h_1 = __float2bfloat16_rn(v1);
                __nv_bfloat16 l_1 = __float2bfloat16_rn(v1 - __bfloat162float(h_1));
                Wh[((h0)     * 128 + r) * 16 + ggl] = h_0;
                Wl[((h0)     * 128 + r) * 16 + ggl] = l_0;
                Wh[((h0 + 1) * 128 + r) * 16 + ggl] = h_1;
                Wl[((h0 + 1) * 128 + r) * 16 + ggl] = l_1;
            }
        }
        __syncthreads();

        // ---- coalesced write-out: [pair][dh][i], i = r*32 + (ch&1)*16 + ggl ----
        __nv_bfloat16* dstH = isK ? g_KThi : g_VThi;
        __nv_bfloat16* dstL = isK ? g_KTlo : g_VTlo;
        const int ibase = (ch & 1) * 16;
        for (int idx = tid; idx < 1024; idx += 256) {
            int h    = idx >> 8;
            int r    = (idx >> 1) & 127;
            int half = idx & 1;
            size_t off = ((size_t)((bb * 4 + h) * DH + dh)) * SEQ + r * 32 + ibase + half * 8;
            int soff = ((h * 128) + r) * 16 + half * 8;
            *(uint4*)&dstH[off] = *(uint4*)&Wh[soff];
            *(uint4*)&dstL[off] = *(uint4*)&Wl[soff];
        }
        __syncthreads();   // staging consumed before next chunk's w load
    }
}

// ---------------------------------------------------------------------------
// Kernel 2: flash attention (proven round-9 HMMA version, unchanged)
// ---------------------------------------------------------------------------
#define KT_PITCH 72
#define VT_PITCH 136
#define KT_ELEMS (64 * KT_PITCH)
#define VT_ELEMS (DH * VT_PITCH)
#define ATTN_SMEM ((KT_ELEMS + 2 * 2 * VT_ELEMS) * 2)   // 44032 bytes

__global__ __launch_bounds__(128, 3) void attn_kernel() {
    extern __shared__ __nv_bfloat16 smb[];
    __nv_bfloat16* KTs = smb;
    __nv_bfloat16* VTs = smb + KT_ELEMS;

    const int p  = blockIdx.y;
    const int i0 = blockIdx.x * 64;
    const int tid  = threadIdx.x;
    const int wid  = tid >> 5;
    const int lane = tid & 31;
    const int mrow = wid * 16;

    const __nv_bfloat16* KTh = g_KThi + (size_t)p * DH * SEQ;
    const __nv_bfloat16* KTl = g_KTlo + (size_t)p * DH * SEQ;
    const __nv_bfloat16* VTh = g_VThi + (size_t)p * DH * SEQ;
    const __nv_bfloat16* VTl = g_VTlo + (size_t)p * DH * SEQ;

    auto prefetch = [&](int s, int j0) {
        for (int t = tid; t < 1024; t += 128) {
            int which = t >> 9;
            int rem = t & 511;
            int d = rem >> 4, q = rem & 15;
            const __nv_bfloat16* src = (which ? VTl : VTh) + (size_t)d * SEQ + j0 + q * 8;
            cp16(VTs + (s * 2 + which) * VT_ELEMS + d * VT_PITCH + q * 8, src);
        }
    };

    prefetch(0, 0);
    for (int t = tid; t < 512; t += 128) {
        int row = t >> 3, q = t & 7;
        const __nv_bfloat16* src = (row < 32 ? KTh : KTl) + (size_t)(row & 31) * SEQ + i0 + q * 8;
        cp16(KTs + row * KT_PITCH + q * 8, src);
    }
    asm volatile("cp.async.commit_group;");
    prefetch(1, 128);
    asm volatile("cp.async.commit_group;");
    asm volatile("cp.async.wait_group 1;");
    __syncthreads();

    const int grp = lane >> 3, l8 = lane & 7;
    uint ahi[2][4], alo[2][4];
    {
        int ar  = (grp >> 1) * 8 + l8;
        int acl = mrow + (grp & 1) * 8;
#pragma unroll
        for (int kt = 0; kt < 2; kt++) {
            ldsm4t(ahi[kt], KTs + (kt * 16 + ar) * KT_PITCH + acl);
            ldsm4t(alo[kt], KTs + (32 + kt * 16 + ar) * KT_PITCH + acl);
        }
    }

    float m[2] = {-1e30f, -1e30f}, l[2] = {0.f, 0.f};
    float acc[4][4];
#pragma unroll
    for (int nt = 0; nt < 4; nt++)
#pragma unroll
        for (int e = 0; e < 4; e++) acc[nt][e] = 0.f;

    const int bkr = (grp & 1) * 8 + l8;
    const int bnc = (grp >> 1) * 8;
    const int pnr = (grp >> 1) * 8 + l8;
    const int pkc = (grp & 1) * 8;

    for (int it = 0; it < 32; it++) {
        const __nv_bfloat16* Vh = VTs + ((it & 1) * 2) * VT_ELEMS;
        const __nv_bfloat16* Vl = Vh + VT_ELEMS;

#pragma unroll
        for (int half = 0; half < 2; half++) {
            const int jh = half * 64;
            float S[8][4];
#pragma unroll
            for (int jt = 0; jt < 8; jt++)
#pragma unroll
                for (int e = 0; e < 4; e++) S[jt][e] = 0.f;

#pragma unroll
            for (int g = 0; g < 4; g++) {
                const int n0 = jh + g * 16 + bnc;
                uint bh0[4], bh1[4], bl0[4], bl1[4];
                ldsm4t(bh0, Vh + (bkr)      * VT_PITCH + n0);
                ldsm4t(bh1, Vh + (16 + bkr) * VT_PITCH + n0);
                ldsm4t(bl0, Vl + (bkr)      * VT_PITCH + n0);
                ldsm4t(bl1, Vl + (16 + bkr) * VT_PITCH + n0);
                float* s0 = S[2 * g];
                float* s1 = S[2 * g + 1];
                mma16816(s0, ahi[0], bh0[0], bh0[1]); mma16816(s0, ahi[1], bh1[0], bh1[1]);
                mma16816(s0, ahi[0], bl0[0], bl0[1]); mma16816(s0, ahi[1], bl1[0], bl1[1]);
                mma16816(s0, alo[0], bh0[0], bh0[1]); mma16816(s0, alo[1], bh1[0], bh1[1]);
                mma16816(s1, ahi[0], bh0[2], bh0[3]); mma16816(s1, ahi[1], bh1[2], bh1[3]);
                mma16816(s1, ahi[0], bl0[2], bl0[3]); mma16816(s1, ahi[1], bl1[2], bl1[3]);
                mma16816(s1, alo[0], bh0[2], bh0[3]); mma16816(s1, alo[1], bh1[2], bh1[3]);
            }

#pragma unroll
            for (int r = 0; r < 2; r++) {
                float mx = -1e30f;
#pragma unroll
                for (int jt = 0; jt < 8; jt++)
                    mx = fmaxf(mx, fmaxf(S[jt][2 * r], S[jt][2 * r + 1]));
                mx = fmaxf(mx, __shfl_xor_sync(0xffffffffu, mx, 1));
                mx = fmaxf(mx, __shfl_xor_sync(0xffffffffu, mx, 2));
                float mnew  = fmaxf(m[r], mx);
                float alpha = __expf(m[r] - mnew);
                m[r] = mnew;
                float rs = 0.f;
#pragma unroll
                for (int jt = 0; jt < 8; jt++) {
                    float e0 = __expf(S[jt][2 * r] - mnew);
                    float e1 = __expf(S[jt][2 * r + 1] - mnew);
                    S[jt][2 * r] = e0; S[jt][2 * r + 1] = e1;
                    rs += e0 + e1;
                }
                rs += __shfl_xor_sync(0xffffffffu, rs, 1);
                rs += __shfl_xor_sync(0xffffffffu, rs, 2);
                l[r] = l[r] * alpha + rs;
#pragma unroll
                for (int nt = 0; nt < 4; nt++) {
                    acc[nt][2 * r]     *= alpha;
                    acc[nt][2 * r + 1] *= alpha;
                }
            }

#pragma unroll
            for (int cch = 0; cch < 4; cch++) {
                float* t0 = S[2 * cch];
                float* t1 = S[2 * cch + 1];
                uint ah[4], al[4];
                ah[0] = packbf(t0[0], t0[1]);  al[0] = packlo(t0[0], t0[1], ah[0]);
                ah[1] = packbf(t0[2], t0[3]);  al[1] = packlo(t0[2], t0[3], ah[1]);
                ah[2] = packbf(t1[0], t1[1]);  al[2] = packlo(t1[0], t1[1], ah[2]);
                ah[3] = packbf(t1[2], t1[3]);  al[3] = packlo(t1[2], t1[3], ah[3]);
                const int k0 = jh + cch * 16 + pkc;
#pragma unroll
                for (int qq = 0; qq < 2; qq++) {
                    uint rh[4], rl[4];
                    ldsm4(rh, Vh + (qq * 16 + pnr) * VT_PITCH + k0);
                    ldsm4(rl, Vl + (qq * 16 + pnr) * VT_PITCH + k0);
                    float* a0 = acc[2 * qq];
                    float* a1 = acc[2 * qq + 1];
                    mma16816(a0, ah, rh[0], rh[1]);
                    mma16816(a0, ah, rl[0], rl[1]);
                    mma16816(a0, al, rh[0], rh[1]);
                    mma16816(a1, ah, rh[2], rh[3]);
                    mma16816(a1, ah, rl[2], rl[3]);
                    mma16816(a1, al, rh[2], rh[3]);
                }
            }
        }

        __syncthreads();
        if (it + 2 < 32) prefetch((it + 2) & 1, (it + 2) * 128);
        asm volatile("cp.async.commit_group;");
        asm volatile("cp.async.wait_group 1;");
        __syncthreads();
    }

    const int b = p >> 2, h = p & 3;
    int row0 = i0 + mrow + (lane >> 2);
    int row1 = row0 + 8;
    float inv0 = 1.f / l[0], inv1 = 1.f / l[1];
#pragma unroll
    for (int nt = 0; nt < 4; nt++) {
#pragma unroll
        for (int e = 0; e < 2; e++) {
            int dhh = nt * 8 + (lane & 3) * 2 + e;
            g_O[((size_t)b * SEQ + row0) * 128 + dhh * 4 + h] = acc[nt][e] * inv0;
            g_O[((size_t)b * SEQ + row1) * 128 + dhh * 4 + h] = acc[nt][2 + e] * inv1;
        }
    }
}

// ---------------------------------------------------------------------------
// Kernel 3: y = O @ w_out + b_out via 3-term bf16 HMMA
// grid 128 (m-tiles of 128), 256 thr, n in 2 chunks of 64
// ---------------------------------------------------------------------------
__global__ __launch_bounds__(256, 1) void proj_out_tc(const float* __restrict__ b_out,
                                                      float* __restrict__ y) {
    extern __shared__ char sm[];
    __nv_bfloat16* Xhi = (__nv_bfloat16*)sm;
    __nv_bfloat16* Xlo = Xhi + 128 * XP;
    __nv_bfloat16* Wh  = Xlo + 128 * XP;
    __nv_bfloat16* Wl  = Wh + 128 * WP;
    float* SF = (float*)Wh;                 // 128x64 fp32 staging (32KB <= 36.8KB)

    const int row0 = blockIdx.x * 128;
    const int tid  = threadIdx.x;
    const int warp = tid >> 5;
    const int lane = tid & 31;
    const int mrow = warp * 16;
    const int grp  = lane >> 3, l8 = lane & 7;
    const int bkr  = (grp & 1) * 8 + l8;
    const int bnc  = (grp >> 1) * 8;

    for (int idx = tid; idx < 128 * 32; idx += 256) {
        int r = idx >> 5, c4 = idx & 31;
        float4 v = *(const float4*)&g_O[(size_t)(row0 + r) * 128 + c4 * 4];
        uint h01 = packbf(v.x, v.y), h23 = packbf(v.z, v.w);
        uint l01 = packlo(v.x, v.y, h01), l23 = packlo(v.z, v.w, h23);
        *(uint2*)&Xhi[r * XP + c4 * 4] = make_uint2(h01, h23);
        *(uint2*)&Xlo[r * XP + c4 * 4] = make_uint2(l01, l23);
    }
    __syncthreads();

    for (int ch = 0; ch < 2; ch++) {
        const int n0 = ch * 64;
        for (int t = tid; t < 2048; t += 256) {
            int which = t >> 10;
            int rem = t & 1023;
            int k = rem >> 3, q = rem & 7;
            __nv_bfloat16* dst = (which ? Wl : Wh) + k * WP + q * 8;
            const __nv_bfloat16* src = (which ? g_WOlo : g_WOhi) + k * 128 + n0 + q * 8;
            cp16(dst, src);
        }
        asm volatile("cp.async.commit_group;");
        asm volatile("cp.async.wait_group 0;");
        __syncthreads();

        float acc[8][4];
#pragma unroll
        for (int t8 = 0; t8 < 8; t8++)
#pragma unroll
            for (int e = 0; e < 4; e++) acc[t8][e] = 0.f;

#pragma unroll
        for (int kc = 0; kc < 8; kc++) {
            uint ahi[4], alo[4];
            int aoff = (mrow + (lane & 15)) * XP + kc * 16 + 8 * (lane >> 4);
            ldsm4(ahi, Xhi + aoff);
            ldsm4(alo, Xlo + aoff);
#pragma unroll
            for (int g = 0; g < 4; g++) {
                uint bh[4], bl[4];
                int boff = (kc * 16 + bkr) * WP + g * 16 + bnc;
                ldsm4t(bh, Wh + boff);
                ldsm4t(bl, Wl + boff);
                float* s0 = acc[2 * g];
                float* s1 = acc[2 * g + 1];
                mma16816(s0, ahi, bh[0], bh[1]);
                mma16816(s0, ahi, bl[0], bl[1]);
                mma16816(s0, alo, bh[0], bh[1]);
                mma16816(s1, ahi, bh[2], bh[3]);
                mma16816(s1, ahi, bl[2], bl[3]);
                mma16816(s1, alo, bh[2], bh[3]);
            }
        }
        __syncthreads();

        const int r0 = mrow + (lane >> 2);
        const int q  = lane & 3;
#pragma unroll
        for (int t8 = 0; t8 < 8; t8++) {
            const int c0 = t8 * 8 + q * 2;
            float bia0 = __ldg(&b_out[ch * 64 + c0]);
            float bia1 = __ldg(&b_out[ch * 64 + c0 + 1]);
#pragma unroll
            for (int rr = 0; rr < 2; rr++) {
                int r = r0 + rr * 8;
                SF[r * 64 + c0]     = acc[t8][rr * 2 + 0] + bia0;
                SF[r * 64 + c0 + 1] = acc[t8][rr * 2 + 1] + bia1;
            }
        }
        __syncthreads();

        for (int idx = tid; idx < 128 * 16; idx += 256) {
            int r = idx >> 4, c4 = idx & 15;
            *(uint4*)&y[(size_t)(row0 + r) * 128 + ch * 64 + c4 * 4] =
                *(uint4*)&SF[r * 64 + c4 * 4];
        }
        __syncthreads();
    }
}

// ---------------------------------------------------------------------------
extern "C" void kernel_launch(void* const* d_in, const int* in_sizes, int n_in,
                              void* d_out, int out_size) {
    const float *x = nullptr, *wq = nullptr, *wo = nullptr, *bo = nullptr;
    for (int idx = 0; idx < n_in; idx++) {
        switch (in_sizes[idx]) {
            case 4 * 16 * 256 * 128: x  = (const float*)d_in[idx]; break;
            case 128 * 384:          wq = (const float*)d_in[idx]; break;
            case 128 * 128:          wo = (const float*)d_in[idx]; break;
            case 128:                bo = (const float*)d_in[idx]; break;
        }
    }
    float* y = (float*)d_out;

    cudaFuncSetAttribute(proj_kv_tc, cudaFuncAttributeMaxDynamicSharedMemorySize, PROJ_SMEM);
    cudaFuncSetAttribute(proj_out_tc, cudaFuncAttributeMaxDynamicSharedMemorySize, PROJ_SMEM);
    cudaFuncSetAttribute(attn_kernel, cudaFuncAttributeMaxDynamicSharedMemorySize, ATTN_SMEM);

    prep_w_kernel<<<32, 256>>>(wq, wo);
    proj_kv_tc<<<128, 256, PROJ_SMEM>>>(x);
    attn_kernel<<<dim3(64, NPAIR), 128, ATTN_SMEM>>>();
    proj_out_tc<<<128, 256, PROJ_SMEM>>>(bo, y);
}

// round 16
// speedup vs baseline: 5.3089x; 1.2292x over previous
#include <cuda_runtime.h>
#include <cuda_bf16.h>
#include <cuda_fp16.h>

typedef unsigned int uint;

#define SEQ   4096
#define DH    32
#define NPAIR 16

// ---------------------------------------------------------------------------
// Device scratch  (K/V now fp16 hi/lo)
// ---------------------------------------------------------------------------
__device__ __half g_KThi[NPAIR * DH * SEQ];
__device__ __half g_KTlo[NPAIR * DH * SEQ];
__device__ __half g_VThi[NPAIR * DH * SEQ];
__device__ __half g_VTlo[NPAIR * DH * SEQ];
__device__ float g_O[4 * SEQ * 128];
// pre-split weights (bf16 hi/lo) for the projection GEMMs
__device__ __nv_bfloat16 g_Whi[128 * 256];
__device__ __nv_bfloat16 g_Wlo[128 * 256];
__device__ __nv_bfloat16 g_WOhi[128 * 128];
__device__ __nv_bfloat16 g_WOlo[128 * 128];

// ---------------------------------------------------------------------------
// PTX helpers
// ---------------------------------------------------------------------------
__device__ __forceinline__ void cp16(void* dst, const void* src) {
    unsigned d = (unsigned)__cvta_generic_to_shared(dst);
    asm volatile("cp.async.cg.shared.global [%0], [%1], 16;" :: "r"(d), "l"(src));
}
__device__ __forceinline__ void ldsm4(uint* r, const void* p) {
    unsigned a = (unsigned)__cvta_generic_to_shared(p);
    asm volatile("ldmatrix.sync.aligned.m8n8.x4.shared.b16 {%0,%1,%2,%3}, [%4];"
                 : "=r"(r[0]), "=r"(r[1]), "=r"(r[2]), "=r"(r[3]) : "r"(a));
}
__device__ __forceinline__ void ldsm4t(uint* r, const void* p) {
    unsigned a = (unsigned)__cvta_generic_to_shared(p);
    asm volatile("ldmatrix.sync.aligned.m8n8.x4.trans.shared.b16 {%0,%1,%2,%3}, [%4];"
                 : "=r"(r[0]), "=r"(r[1]), "=r"(r[2]), "=r"(r[3]) : "r"(a));
}
// bf16 mma (projections)
__device__ __forceinline__ void mma16816(float* c, const uint* a, uint b0, uint b1) {
    asm volatile("mma.sync.aligned.m16n8k16.row.col.f32.bf16.bf16.f32 "
                 "{%0,%1,%2,%3},{%4,%5,%6,%7},{%8,%9},{%0,%1,%2,%3};"
                 : "+f"(c[0]), "+f"(c[1]), "+f"(c[2]), "+f"(c[3])
                 : "r"(a[0]), "r"(a[1]), "r"(a[2]), "r"(a[3]), "r"(b0), "r"(b1));
}
// fp16 mma (attention)
__device__ __forceinline__ void mma16816h(float* c, const uint* a, uint b0, uint b1) {
    asm volatile("mma.sync.aligned.m16n8k16.row.col.f32.f16.f16.f32 "
                 "{%0,%1,%2,%3},{%4,%5,%6,%7},{%8,%9},{%0,%1,%2,%3};"
                 : "+f"(c[0]), "+f"(c[1]), "+f"(c[2]), "+f"(c[3])
                 : "r"(a[0]), "r"(a[1]), "r"(a[2]), "r"(a[3]), "r"(b0), "r"(b1));
}
__device__ __forceinline__ uint packbf(float x, float y) {
    __nv_bfloat162 t = __floats2bfloat162_rn(x, y);
    return *(uint*)&t;
}
__device__ __forceinline__ uint packlo(float x, float y, uint hi) {
    __nv_bfloat162 h = *(__nv_bfloat162*)&hi;
    return packbf(x - __bfloat162float(h.x), y - __bfloat162float(h.y));
}
__device__ __forceinline__ uint packh(float x, float y) {
    __half2 t = __floats2half2_rn(x, y);
    return *(uint*)&t;
}

// ---------------------------------------------------------------------------
// Kernel 0: split weights into bf16 hi/lo
// ---------------------------------------------------------------------------
__global__ __launch_bounds__(256) void prep_w_kernel(const float* __restrict__ w_qkv,
                                                     const float* __restrict__ w_out) {
    int t0 = blockIdx.x * 256 + threadIdx.x;
    for (int i = t0; i < 128 * 256; i += gridDim.x * 256) {
        int k = i >> 8, n = i & 255;
        float v = w_qkv[k * 384 + 128 + n];
        __nv_bfloat16 hi = __float2bfloat16_rn(v);
        g_Whi[i] = hi;
        g_Wlo[i] = __float2bfloat16_rn(v - __bfloat162float(hi));
    }
    for (int i = t0; i < 128 * 128; i += gridDim.x * 256) {
        float v = w_out[i];
        __nv_bfloat16 hi = __float2bfloat16_rn(v);
        g_WOhi[i] = hi;
        g_WOlo[i] = __float2bfloat16_rn(v - __bfloat162float(hi));
    }
}

// ---------------------------------------------------------------------------
// Kernel 1: kv projection (3-term bf16 HMMA) + l2 norm + fp16 hi/lo + scatter
// grid (128 m-tiles, 4 chunks): chunk 0,1 = K channels; 2,3 = V channels
// ---------------------------------------------------------------------------
#define XP 136
#define WP 72
#define PROJ_SMEM ((2 * 128 * XP + 2 * 128 * WP) * 2)   // 106496 B

__global__ __launch_bounds__(256, 1) void proj_kv_tc(const float* __restrict__ x) {
    extern __shared__ char sm[];
    __nv_bfloat16* Xhi = (__nv_bfloat16*)sm;
    __nv_bfloat16* Xlo = Xhi + 128 * XP;
    __nv_bfloat16* Wh  = Xlo + 128 * XP;
    __nv_bfloat16* Wl  = Wh + 128 * WP;

    const int row0 = blockIdx.x * 128;
    const int ch   = blockIdx.y;
    const int tid  = threadIdx.x;
    const int warp = tid >> 5;
    const int lane = tid & 31;
    const int mrow = warp * 16;
    const int grp  = lane >> 3, l8 = lane & 7;
    const int bkr  = (grp & 1) * 8 + l8;
    const int bnc  = (grp >> 1) * 8;
    const int n0   = ch * 64;

    // w chunk (start async before x conversion)
    for (int t = tid; t < 2048; t += 256) {
        int which = t >> 10;
        int rem = t & 1023;
        int k = rem >> 3, q = rem & 7;
        __nv_bfloat16* dst = (which ? Wl : Wh) + k * WP + q * 8;
        const __nv_bfloat16* src = (which ? g_Wlo : g_Whi) + k * 256 + n0 + q * 8;
        cp16(dst, src);
    }
    asm volatile("cp.async.commit_group;");

    for (int idx = tid; idx < 128 * 32; idx += 256) {
        int r = idx >> 5, c4 = idx & 31;
        float4 v = *(const float4*)&x[(size_t)(row0 + r) * 128 + c4 * 4];
        uint h01 = packbf(v.x, v.y), h23 = packbf(v.z, v.w);
        uint l01 = packlo(v.x, v.y, h01), l23 = packlo(v.z, v.w, h23);
        *(uint2*)&Xhi[r * XP + c4 * 4] = make_uint2(h01, h23);
        *(uint2*)&Xlo[r * XP + c4 * 4] = make_uint2(l01, l23);
    }
    asm volatile("cp.async.wait_group 0;");
    __syncthreads();

    const int bb = row0 >> 12;
    const int dh = (row0 & 4095) >> 7;

    float acc[8][4];
#pragma unroll
    for (int t8 = 0; t8 < 8; t8++)
#pragma unroll
        for (int e = 0; e < 4; e++) acc[t8][e] = 0.f;

#pragma unroll
    for (int kc = 0; kc < 8; kc++) {
        uint ahi[4], alo[4];
        int aoff = (mrow + (lane & 15)) * XP + kc * 16 + 8 * (lane >> 4);
        ldsm4(ahi, Xhi + aoff);
        ldsm4(alo, Xlo + aoff);
#pragma unroll
        for (int g = 0; g < 4; g++) {
            uint bh[4], bl[4];
            int boff = (kc * 16 + bkr) * WP + g * 16 + bnc;
            ldsm4t(bh, Wh + boff);
            ldsm4t(bl, Wl + boff);
            float* s0 = acc[2 * g];
            float* s1 = acc[2 * g + 1];
            mma16816(s0, ahi, bh[0], bh[1]);
            mma16816(s0, ahi, bl[0], bl[1]);
            mma16816(s0, alo, bh[0], bh[1]);
            mma16816(s1, ahi, bh[2], bh[3]);
            mma16816(s1, ahi, bl[2], bl[3]);
            mma16816(s1, alo, bh[2], bh[3]);
        }
    }
    __syncthreads();   // Wh/Wl reads done -> reuse as fp16 staging

    __half* SWh = (__half*)Wh;
    __half* SWl = (__half*)Wl;
    const bool isK = (ch < 2);
    const int r0 = mrow + (lane >> 2);
    const int q  = lane & 3;
#pragma unroll
    for (int t8 = 0; t8 < 8; t8++) {
        const int c0  = t8 * 8 + q * 2;
        const int h0  = c0 & 3;
        const int ggl = c0 >> 2;
#pragma unroll
        for (int rr = 0; rr < 2; rr++) {
            float v0 = acc[t8][rr * 2 + 0];
            float v1 = acc[t8][rr * 2 + 1];
            if (isK) {
                float ss = v0 * v0 + v1 * v1;
                ss += __shfl_xor_sync(0xffffffffu, ss, 1);
                float inv = 10.f / fmaxf(sqrtf(ss), 1e-12f);
                v0 *= inv; v1 *= inv;
            }
            int r = r0 + rr * 8;
            __half h_0 = __float2half_rn(v0);
            __half l_0 = __float2half_rn(v0 - __half2float(h_0));
            __half h_1 = __float2half_rn(v1);
            __half l_1 = __float2half_rn(v1 - __half2float(h_1));
            SWh[((h0)     * 128 + r) * 16 + ggl] = h_0;
            SWl[((h0)     * 128 + r) * 16 + ggl] = l_0;
            SWh[((h0 + 1) * 128 + r) * 16 + ggl] = h_1;
            SWl[((h0 + 1) * 128 + r) * 16 + ggl] = l_1;
        }
    }
    __syncthreads();

    __half* dstH = isK ? g_KThi : g_VThi;
    __half* dstL = isK ? g_KTlo : g_VTlo;
    const int ibase = (ch & 1) * 16;
    for (int idx = tid; idx < 1024; idx += 256) {
        int h    = idx >> 8;
        int r    = (idx >> 1) & 127;
        int half = idx & 1;
        size_t off = ((size_t)((bb * 4 + h) * DH + dh)) * SEQ + r * 32 + ibase + half * 8;
        int soff = ((h * 128) + r) * 16 + half * 8;
        *(uint4*)&dstH[off] = *(uint4*)&SWh[soff];
        *(uint4*)&dstL[off] = *(uint4*)&SWl[soff];
    }
}

// ---------------------------------------------------------------------------
// Kernel 2: flash attention, fp16 HMMA. S 3-term, PV single-term (P,V fp16).
// ---------------------------------------------------------------------------
#define KT_PITCH 72
#define VT_PITCH 136
#define KT_ELEMS (64 * KT_PITCH)
#define VT_ELEMS (DH * VT_PITCH)
#define ATTN_SMEM ((KT_ELEMS + 2 * 2 * VT_ELEMS) * 2)   // 44032 bytes

__global__ __launch_bounds__(128, 3) void attn_kernel() {
    extern __shared__ __half smh[];
    __half* KTs = smh;                    // [64][72]: rows 0-31 Khi, 32-63 Klo
    __half* VTs = smh + KT_ELEMS;         // [2 stages][2 hi/lo][32][136]

    const int p  = blockIdx.y;
    const int i0 = blockIdx.x * 64;
    const int tid  = threadIdx.x;
    const int wid  = tid >> 5;
    const int lane = tid & 31;
    const int mrow = wid * 16;

    const __half* KTh = g_KThi + (size_t)p * DH * SEQ;
    const __half* KTl = g_KTlo + (size_t)p * DH * SEQ;
    const __half* VTh = g_VThi + (size_t)p * DH * SEQ;
    const __half* VTl = g_VTlo + (size_t)p * DH * SEQ;

    auto prefetch = [&](int s, int j0) {
        for (int t = tid; t < 1024; t += 128) {
            int which = t >> 9;
            int rem = t & 511;
            int d = rem >> 4, q = rem & 15;
            const __half* src = (which ? VTl : VTh) + (size_t)d * SEQ + j0 + q * 8;
            cp16(VTs + (s * 2 + which) * VT_ELEMS + d * VT_PITCH + q * 8, src);
        }
    };

    prefetch(0, 0);
    for (int t = tid; t < 512; t += 128) {
        int row = t >> 3, q = t & 7;
        const __half* src = (row < 32 ? KTh : KTl) + (size_t)(row & 31) * SEQ + i0 + q * 8;
        cp16(KTs + row * KT_PITCH + q * 8, src);
    }
    asm volatile("cp.async.commit_group;");
    prefetch(1, 128);
    asm volatile("cp.async.commit_group;");
    asm volatile("cp.async.wait_group 1;");
    __syncthreads();

    const int grp = lane >> 3, l8 = lane & 7;
    uint ahi[2][4], alo[2][4];
    {
        int ar  = (grp >> 1) * 8 + l8;
        int acl = mrow + (grp & 1) * 8;
#pragma unroll
        for (int kt = 0; kt < 2; kt++) {
            ldsm4t(ahi[kt], KTs + (kt * 16 + ar) * KT_PITCH + acl);
            ldsm4t(alo[kt], KTs + (32 + kt * 16 + ar) * KT_PITCH + acl);
        }
    }

    float m[2] = {-1e30f, -1e30f}, l[2] = {0.f, 0.f};
    float acc[4][4];
#pragma unroll
    for (int nt = 0; nt < 4; nt++)
#pragma unroll
        for (int e = 0; e < 4; e++) acc[nt][e] = 0.f;

    const int bkr = (grp & 1) * 8 + l8;
    const int bnc = (grp >> 1) * 8;
    const int pnr = (grp >> 1) * 8 + l8;
    const int pkc = (grp & 1) * 8;

    for (int it = 0; it < 32; it++) {
        const __half* Vh = VTs + ((it & 1) * 2) * VT_ELEMS;
        const __half* Vl = Vh + VT_ELEMS;

#pragma unroll
        for (int half = 0; half < 2; half++) {
            const int jh = half * 64;
            float S[8][4];
#pragma unroll
            for (int jt = 0; jt < 8; jt++)
#pragma unroll
                for (int e = 0; e < 4; e++) S[jt][e] = 0.f;

            // ---- S = Khi.Vhi + Khi.Vlo + Klo.Vhi (all fp16) ----
#pragma unroll
            for (int g = 0; g < 4; g++) {
                const int n0 = jh + g * 16 + bnc;
                uint bh0[4], bh1[4], bl0[4], bl1[4];
                ldsm4t(bh0, Vh + (bkr)      * VT_PITCH + n0);
                ldsm4t(bh1, Vh + (16 + bkr) * VT_PITCH + n0);
                ldsm4t(bl0, Vl + (bkr)      * VT_PITCH + n0);
                ldsm4t(bl1, Vl + (16 + bkr) * VT_PITCH + n0);
                float* s0 = S[2 * g];
                float* s1 = S[2 * g + 1];
                mma16816h(s0, ahi[0], bh0[0], bh0[1]); mma16816h(s0, ahi[1], bh1[0], bh1[1]);
                mma16816h(s0, ahi[0], bl0[0], bl0[1]); mma16816h(s0, ahi[1], bl1[0], bl1[1]);
                mma16816h(s0, alo[0], bh0[0], bh0[1]); mma16816h(s0, alo[1], bh1[0], bh1[1]);
                mma16816h(s1, ahi[0], bh0[2], bh0[3]); mma16816h(s1, ahi[1], bh1[2], bh1[3]);
                mma16816h(s1, ahi[0], bl0[2], bl0[3]); mma16816h(s1, ahi[1], bl1[2], bl1[3]);
                mma16816h(s1, alo[0], bh0[2], bh0[3]); mma16816h(s1, alo[1], bh1[2], bh1[3]);
            }

            // ---- online softmax ----
#pragma unroll
            for (int r = 0; r < 2; r++) {
                float mx = -1e30f;
#pragma unroll
                for (int jt = 0; jt < 8; jt++)
                    mx = fmaxf(mx, fmaxf(S[jt][2 * r], S[jt][2 * r + 1]));
                mx = fmaxf(mx, __shfl_xor_sync(0xffffffffu, mx, 1));
                mx = fmaxf(mx, __shfl_xor_sync(0xffffffffu, mx, 2));
                float mnew  = fmaxf(m[r], mx);
                float alpha = __expf(m[r] - mnew);
                m[r] = mnew;
                float rs = 0.f;
#pragma unroll
                for (int jt = 0; jt < 8; jt++) {
                    float e0 = __expf(S[jt][2 * r] - mnew);
                    float e1 = __expf(S[jt][2 * r + 1] - mnew);
                    S[jt][2 * r] = e0; S[jt][2 * r + 1] = e1;
                    rs += e0 + e1;
                }
                rs += __shfl_xor_sync(0xffffffffu, rs, 1);
                rs += __shfl_xor_sync(0xffffffffu, rs, 2);
                l[r] = l[r] * alpha + rs;
#pragma unroll
                for (int nt = 0; nt < 4; nt++) {
                    acc[nt][2 * r]     *= alpha;
                    acc[nt][2 * r + 1] *= alpha;
                }
            }

            // ---- PV: acc += P_f16 . Vhi_f16 (single term) ----
#pragma unroll
            for (int cch = 0; cch < 4; cch++) {
                float* t0 = S[2 * cch];
                float* t1 = S[2 * cch + 1];
                uint ah[4];
                ah[0] = packh(t0[0], t0[1]);
                ah[1] = packh(t0[2], t0[3]);
                ah[2] = packh(t1[0], t1[1]);
                ah[3] = packh(t1[2], t1[3]);
                const int k0 = jh + cch * 16 + pkc;
#pragma unroll
                for (int qq = 0; qq < 2; qq++) {
                    uint rh[4];
                    ldsm4(rh, Vh + (qq * 16 + pnr) * VT_PITCH + k0);
                    mma16816h(acc[2 * qq],     ah, rh[0], rh[1]);
                    mma16816h(acc[2 * qq + 1], ah, rh[2], rh[3]);
                }
            }
        }

        __syncthreads();
        if (it + 2 < 32) prefetch((it + 2) & 1, (it + 2) * 128);
        asm volatile("cp.async.commit_group;");
        asm volatile("cp.async.wait_group 1;");
        __syncthreads();
    }

    const int b = p >> 2, h = p & 3;
    int row0 = i0 + mrow + (lane >> 2);
    int row1 = row0 + 8;
    float inv0 = 1.f / l[0], inv1 = 1.f / l[1];
#pragma unroll
    for (int nt = 0; nt < 4; nt++) {
#pragma unroll
        for (int e = 0; e < 2; e++) {
            int dhh = nt * 8 + (lane & 3) * 2 + e;
            g_O[((size_t)b * SEQ + row0) * 128 + dhh * 4 + h] = acc[nt][e] * inv0;
            g_O[((size_t)b * SEQ + row1) * 128 + dhh * 4 + h] = acc[nt][2 + e] * inv1;
        }
    }
}

// ---------------------------------------------------------------------------
// Kernel 3: y = O @ w_out + b_out (3-term bf16 HMMA); grid (128, 2 chunks)
// ---------------------------------------------------------------------------
__global__ __launch_bounds__(256, 1) void proj_out_tc(const float* __restrict__ b_out,
                                                      float* __restrict__ y) {
    extern __shared__ char sm[];
    __nv_bfloat16* Xhi = (__nv_bfloat16*)sm;
    __nv_bfloat16* Xlo = Xhi + 128 * XP;
    __nv_bfloat16* Wh  = Xlo + 128 * XP;
    __nv_bfloat16* Wl  = Wh + 128 * WP;
    float* SF = (float*)Wh;

    const int row0 = blockIdx.x * 128;
    const int ch   = blockIdx.y;
    const int tid  = threadIdx.x;
    const int warp = tid >> 5;
    const int lane = tid & 31;
    const int mrow = warp * 16;
    const int grp  = lane >> 3, l8 = lane & 7;
    const int bkr  = (grp & 1) * 8 + l8;
    const int bnc  = (grp >> 1) * 8;
    const int n0   = ch * 64;

    for (int t = tid; t < 2048; t += 256) {
        int which = t >> 10;
        int rem = t & 1023;
        int k = rem >> 3, q = rem & 7;
        __nv_bfloat16* dst = (which ? Wl : Wh) + k * WP + q * 8;
        const __nv_bfloat16* src = (which ? g_WOlo : g_WOhi) + k * 128 + n0 + q * 8;
        cp16(dst, src);
    }
    asm volatile("cp.async.commit_group;");

    for (int idx = tid; idx < 128 * 32; idx += 256) {
        int r = idx >> 5, c4 = idx & 31;
        float4 v = *(const float4*)&g_O[(size_t)(row0 + r) * 128 + c4 * 4];
        uint h01 = packbf(v.x, v.y), h23 = packbf(v.z, v.w);
        uint l01 = packlo(v.x, v.y, h01), l23 = packlo(v.z, v.w, h23);
        *(uint2*)&Xhi[r * XP + c4 * 4] = make_uint2(h01, h23);
        *(uint2*)&Xlo[r * XP + c4 * 4] = make_uint2(l01, l23);
    }
    asm volatile("cp.async.wait_group 0;");
    __syncthreads();

    float acc[8][4];
#pragma unroll
    for (int t8 = 0; t8 < 8; t8++)
#pragma unroll
        for (int e = 0; e < 4; e++) acc[t8][e] = 0.f;

#pragma unroll
    for (int kc = 0; kc < 8; kc++) {
        uint ahi[4], alo[4];
        int aoff = (mrow + (lane & 15)) * XP + kc * 16 + 8 * (lane >> 4);
        ldsm4(ahi, Xhi + aoff);
        ldsm4(alo, Xlo + aoff);
#pragma unroll
        for (int g = 0; g < 4; g++) {
            uint bh[4], bl[4];
            int boff = (kc * 16 + bkr) * WP + g * 16 + bnc;
            ldsm4t(bh, Wh + boff);
            ldsm4t(bl, Wl + boff);
            float* s0 = acc[2 * g];
            float* s1 = acc[2 * g + 1];
            mma16816(s0, ahi, bh[0], bh[1]);
            mma16816(s0, ahi, bl[0], bl[1]);
            mma16816(s0, alo, bh[0], bh[1]);
            mma16816(s1, ahi, bh[2], bh[3]);
            mma16816(s1, ahi, bl[2], bl[3]);
            mma16816(s1, alo, bh[2], bh[3]);
        }
    }
    __syncthreads();

    const int r0 = mrow + (lane >> 2);
    const int q  = lane & 3;
#pragma unroll
    for (int t8 = 0; t8 < 8; t8++) {
        const int c0 = t8 * 8 + q * 2;
        float bia0 = __ldg(&b_out[n0 + c0]);
        float bia1 = __ldg(&b_out[n0 + c0 + 1]);
#pragma unroll
        for (int rr = 0; rr < 2; rr++) {
            int r = r0 + rr * 8;
            SF[r * 64 + c0]     = acc[t8][rr * 2 + 0] + bia0;
            SF[r * 64 + c0 + 1] = acc[t8][rr * 2 + 1] + bia1;
        }
    }
    __syncthreads();

    for (int idx = tid; idx < 128 * 16; idx += 256) {
        int r = idx >> 4, c4 = idx & 15;
        *(uint4*)&y[(size_t)(row0 + r) * 128 + n0 + c4 * 4] = *(uint4*)&SF[r * 64 + c4 * 4];
    }
}

// ---------------------------------------------------------------------------
extern "C" void kernel_launch(void* const* d_in, const int* in_sizes, int n_in,
                              void* d_out, int out_size) {
    const float *x = nullptr, *wq = nullptr, *wo = nullptr, *bo = nullptr;
    for (int idx = 0; idx < n_in; idx++) {
        switch (in_sizes[idx]) {
            case 4 * 16 * 256 * 128: x  = (const float*)d_in[idx]; break;
            case 128 * 384:          wq = (const float*)d_in[idx]; break;
            case 128 * 128:          wo = (const float*)d_in[idx]; break;
            case 128:                bo = (const float*)d_in[idx]; break;
        }
    }
    float* y = (float*)d_out;

    cudaFuncSetAttribute(proj_kv_tc, cudaFuncAttributeMaxDynamicSharedMemorySize, PROJ_SMEM);
    cudaFuncSetAttribute(proj_out_tc, cudaFuncAttributeMaxDynamicSharedMemorySize, PROJ_SMEM);
    cudaFuncSetAttribute(attn_kernel, cudaFuncAttributeMaxDynamicSharedMemorySize, ATTN_SMEM);

    prep_w_kernel<<<32, 256>>>(wq, wo);
    proj_kv_tc<<<dim3(128, 4), 256, PROJ_SMEM>>>(x);
    attn_kernel<<<dim3(64, NPAIR), 128, ATTN_SMEM>>>();
    proj_out_tc<<<dim3(128, 2), 256, PROJ_SMEM>>>(bo, y);
}

// round 17
// speedup vs baseline: 5.4924x; 1.0346x over previous
#include <cuda_runtime.h>
#include <cuda_bf16.h>
#include <cuda_fp16.h>

typedef unsigned int uint;

#define SEQ   4096
#define DH    32
#define NPAIR 16

// ---------------------------------------------------------------------------
// Device scratch  (K/V fp16 hi/lo; K carries 10*log2e scale)
// ---------------------------------------------------------------------------
__device__ __half g_KThi[NPAIR * DH * SEQ];
__device__ __half g_KTlo[NPAIR * DH * SEQ];
__device__ __half g_VThi[NPAIR * DH * SEQ];
__device__ __half g_VTlo[NPAIR * DH * SEQ];
__device__ float g_O[4 * SEQ * 128];
__device__ __nv_bfloat16 g_Whi[128 * 256];
__device__ __nv_bfloat16 g_Wlo[128 * 256];
__device__ __nv_bfloat16 g_WOhi[128 * 128];
__device__ __nv_bfloat16 g_WOlo[128 * 128];

// ---------------------------------------------------------------------------
// PTX helpers
// ---------------------------------------------------------------------------
__device__ __forceinline__ void cp16(void* dst, const void* src) {
    unsigned d = (unsigned)__cvta_generic_to_shared(dst);
    asm volatile("cp.async.cg.shared.global [%0], [%1], 16;" :: "r"(d), "l"(src));
}
__device__ __forceinline__ void ldsm4(uint* r, const void* p) {
    unsigned a = (unsigned)__cvta_generic_to_shared(p);
    asm volatile("ldmatrix.sync.aligned.m8n8.x4.shared.b16 {%0,%1,%2,%3}, [%4];"
                 : "=r"(r[0]), "=r"(r[1]), "=r"(r[2]), "=r"(r[3]) : "r"(a));
}
__device__ __forceinline__ void ldsm4t(uint* r, const void* p) {
    unsigned a = (unsigned)__cvta_generic_to_shared(p);
    asm volatile("ldmatrix.sync.aligned.m8n8.x4.trans.shared.b16 {%0,%1,%2,%3}, [%4];"
                 : "=r"(r[0]), "=r"(r[1]), "=r"(r[2]), "=r"(r[3]) : "r"(a));
}
__device__ __forceinline__ void mma16816(float* c, const uint* a, uint b0, uint b1) {
    asm volatile("mma.sync.aligned.m16n8k16.row.col.f32.bf16.bf16.f32 "
                 "{%0,%1,%2,%3},{%4,%5,%6,%7},{%8,%9},{%0,%1,%2,%3};"
                 : "+f"(c[0]), "+f"(c[1]), "+f"(c[2]), "+f"(c[3])
                 : "r"(a[0]), "r"(a[1]), "r"(a[2]), "r"(a[3]), "r"(b0), "r"(b1));
}
__device__ __forceinline__ void mma16816h(float* c, const uint* a, uint b0, uint b1) {
    asm volatile("mma.sync.aligned.m16n8k16.row.col.f32.f16.f16.f32 "
                 "{%0,%1,%2,%3},{%4,%5,%6,%7},{%8,%9},{%0,%1,%2,%3};"
                 : "+f"(c[0]), "+f"(c[1]), "+f"(c[2]), "+f"(c[3])
                 : "r"(a[0]), "r"(a[1]), "r"(a[2]), "r"(a[3]), "r"(b0), "r"(b1));
}
__device__ __forceinline__ uint packbf(float x, float y) {
    __nv_bfloat162 t = __floats2bfloat162_rn(x, y);
    return *(uint*)&t;
}
__device__ __forceinline__ uint packlo(float x, float y, uint hi) {
    __nv_bfloat162 h = *(__nv_bfloat162*)&hi;
    return packbf(x - __bfloat162float(h.x), y - __bfloat162float(h.y));
}
__device__ __forceinline__ uint packh(float x, float y) {
    __half2 t = __floats2half2_rn(x, y);
    return *(uint*)&t;
}

// ---------------------------------------------------------------------------
// Kernel 0: split weights into bf16 hi/lo
// ---------------------------------------------------------------------------
__global__ __launch_bounds__(256) void prep_w_kernel(const float* __restrict__ w_qkv,
                                                     const float* __restrict__ w_out) {
    int t0 = blockIdx.x * 256 + threadIdx.x;
    for (int i = t0; i < 128 * 256; i += gridDim.x * 256) {
        int k = i >> 8, n = i & 255;
        float v = w_qkv[k * 384 + 128 + n];
        __nv_bfloat16 hi = __float2bfloat16_rn(v);
        g_Whi[i] = hi;
        g_Wlo[i] = __float2bfloat16_rn(v - __bfloat162float(hi));
    }
    for (int i = t0; i < 128 * 128; i += gridDim.x * 256) {
        float v = w_out[i];
        __nv_bfloat16 hi = __float2bfloat16_rn(v);
        g_WOhi[i] = hi;
        g_WOlo[i] = __float2bfloat16_rn(v - __bfloat162float(hi));
    }
}

// ---------------------------------------------------------------------------
// Kernel 1: kv projection (3-term bf16 HMMA) + l2 norm + fp16 hi/lo + scatter
// K post-norm scale = 10*log2e so the attention softmax can use exp2.
// ---------------------------------------------------------------------------
#define XP 136
#define WP 72
#define PROJ_SMEM ((2 * 128 * XP + 2 * 128 * WP) * 2)   // 106496 B

__global__ __launch_bounds__(256, 1) void proj_kv_tc(const float* __restrict__ x) {
    extern __shared__ char sm[];
    __nv_bfloat16* Xhi = (__nv_bfloat16*)sm;
    __nv_bfloat16* Xlo = Xhi + 128 * XP;
    __nv_bfloat16* Wh  = Xlo + 128 * XP;
    __nv_bfloat16* Wl  = Wh + 128 * WP;

    const int row0 = blockIdx.x * 128;
    const int ch   = blockIdx.y;
    const int tid  = threadIdx.x;
    const int warp = tid >> 5;
    const int lane = tid & 31;
    const int mrow = warp * 16;
    const int grp  = lane >> 3, l8 = lane & 7;
    const int bkr  = (grp & 1) * 8 + l8;
    const int bnc  = (grp >> 1) * 8;
    const int n0   = ch * 64;

    for (int t = tid; t < 2048; t += 256) {
        int which = t >> 10;
        int rem = t & 1023;
        int k = rem >> 3, q = rem & 7;
        __nv_bfloat16* dst = (which ? Wl : Wh) + k * WP + q * 8;
        const __nv_bfloat16* src = (which ? g_Wlo : g_Whi) + k * 256 + n0 + q * 8;
        cp16(dst, src);
    }
    asm volatile("cp.async.commit_group;");

    for (int idx = tid; idx < 128 * 32; idx += 256) {
        int r = idx >> 5, c4 = idx & 31;
        float4 v = *(const float4*)&x[(size_t)(row0 + r) * 128 + c4 * 4];
        uint h01 = packbf(v.x, v.y), h23 = packbf(v.z, v.w);
        uint l01 = packlo(v.x, v.y, h01), l23 = packlo(v.z, v.w, h23);
        *(uint2*)&Xhi[r * XP + c4 * 4] = make_uint2(h01, h23);
        *(uint2*)&Xlo[r * XP + c4 * 4] = make_uint2(l01, l23);
    }
    asm volatile("cp.async.wait_group 0;");
    __syncthreads();

    const int bb = row0 >> 12;
    const int dh = (row0 & 4095) >> 7;

    float acc[8][4];
#pragma unroll
    for (int t8 = 0; t8 < 8; t8++)
#pragma unroll
        for (int e = 0; e < 4; e++) acc[t8][e] = 0.f;

#pragma unroll
    for (int kc = 0; kc < 8; kc++) {
        uint ahi[4], alo[4];
        int aoff = (mrow + (lane & 15)) * XP + kc * 16 + 8 * (lane >> 4);
        ldsm4(ahi, Xhi + aoff);
        ldsm4(alo, Xlo + aoff);
#pragma unroll
        for (int g = 0; g < 4; g++) {
            uint bh[4], bl[4];
            int boff = (kc * 16 + bkr) * WP + g * 16 + bnc;
            ldsm4t(bh, Wh + boff);
            ldsm4t(bl, Wl + boff);
            float* s0 = acc[2 * g];
            float* s1 = acc[2 * g + 1];
            mma16816(s0, ahi, bh[0], bh[1]);
            mma16816(s0, ahi, bl[0], bl[1]);
            mma16816(s0, alo, bh[0], bh[1]);
            mma16816(s1, ahi, bh[2], bh[3]);
            mma16816(s1, ahi, bl[2], bl[3]);
            mma16816(s1, alo, bh[2], bh[3]);
        }
    }
    __syncthreads();

    __half* SWh = (__half*)Wh;
    __half* SWl = (__half*)Wl;
    const bool isK = (ch < 2);
    const int r0 = mrow + (lane >> 2);
    const int q  = lane & 3;
#pragma unroll
    for (int t8 = 0; t8 < 8; t8++) {
        const int c0  = t8 * 8 + q * 2;
        const int h0  = c0 & 3;
        const int ggl = c0 >> 2;
#pragma unroll
        for (int rr = 0; rr < 2; rr++) {
            float v0 = acc[t8][rr * 2 + 0];
            float v1 = acc[t8][rr * 2 + 1];
            if (isK) {
                float ss = v0 * v0 + v1 * v1;
                ss += __shfl_xor_sync(0xffffffffu, ss, 1);
                // 10 * log2(e): softmax later uses exp2
                float inv = 14.4269504089f / fmaxf(sqrtf(ss), 1e-12f);
                v0 *= inv; v1 *= inv;
            }
            int r = r0 + rr * 8;
            __half h_0 = __float2half_rn(v0);
            __half l_0 = __float2half_rn(v0 - __half2float(h_0));
            __half h_1 = __float2half_rn(v1);
            __half l_1 = __float2half_rn(v1 - __half2float(h_1));
            SWh[((h0)     * 128 + r) * 16 + ggl] = h_0;
            SWl[((h0)     * 128 + r) * 16 + ggl] = l_0;
            SWh[((h0 + 1) * 128 + r) * 16 + ggl] = h_1;
            SWl[((h0 + 1) * 128 + r) * 16 + ggl] = l_1;
        }
    }
    __syncthreads();

    __half* dstH = isK ? g_KThi : g_VThi;
    __half* dstL = isK ? g_KTlo : g_VTlo;
    const int ibase = (ch & 1) * 16;
    for (int idx = tid; idx < 1024; idx += 256) {
        int h    = idx >> 8;
        int r    = (idx >> 1) & 127;
        int half = idx & 1;
        size_t off = ((size_t)((bb * 4 + h) * DH + dh)) * SEQ + r * 32 + ibase + half * 8;
        int soff = ((h * 128) + r) * 16 + half * 8;
        *(uint4*)&dstH[off] = *(uint4*)&SWh[soff];
        *(uint4*)&dstL[off] = *(uint4*)&SWl[soff];
    }
}

// ---------------------------------------------------------------------------
// Kernel 2: flash attention, fp16 HMMA. S 3-term, PV 1-term, base-2 softmax.
// 4 CTAs/SM (smem 44KB x 4 = 176KB).
// ---------------------------------------------------------------------------
#define KT_PITCH 72
#define VT_PITCH 136
#define KT_ELEMS (64 * KT_PITCH)
#define VT_ELEMS (DH * VT_PITCH)
#define ATTN_SMEM ((KT_ELEMS + 2 * 2 * VT_ELEMS) * 2)   // 44032 bytes

__global__ __launch_bounds__(128, 4) void attn_kernel() {
    extern __shared__ __half smh[];
    __half* KTs = smh;
    __half* VTs = smh + KT_ELEMS;

    const int p  = blockIdx.y;
    const int i0 = blockIdx.x * 64;
    const int tid  = threadIdx.x;
    const int wid  = tid >> 5;
    const int lane = tid & 31;
    const int mrow = wid * 16;

    const __half* KTh = g_KThi + (size_t)p * DH * SEQ;
    const __half* KTl = g_KTlo + (size_t)p * DH * SEQ;
    const __half* VTh = g_VThi + (size_t)p * DH * SEQ;
    const __half* VTl = g_VTlo + (size_t)p * DH * SEQ;

    auto prefetch = [&](int s, int j0) {
        for (int t = tid; t < 1024; t += 128) {
            int which = t >> 9;
            int rem = t & 511;
            int d = rem >> 4, q = rem & 15;
            const __half* src = (which ? VTl : VTh) + (size_t)d * SEQ + j0 + q * 8;
            cp16(VTs + (s * 2 + which) * VT_ELEMS + d * VT_PITCH + q * 8, src);
        }
    };

    prefetch(0, 0);
    for (int t = tid; t < 512; t += 128) {
        int row = t >> 3, q = t & 7;
        const __half* src = (row < 32 ? KTh : KTl) + (size_t)(row & 31) * SEQ + i0 + q * 8;
        cp16(KTs + row * KT_PITCH + q * 8, src);
    }
    asm volatile("cp.async.commit_group;");
    prefetch(1, 128);
    asm volatile("cp.async.commit_group;");
    asm volatile("cp.async.wait_group 1;");
    __syncthreads();

    const int grp = lane >> 3, l8 = lane & 7;
    uint ahi[2][4], alo[2][4];
    {
        int ar  = (grp >> 1) * 8 + l8;
        int acl = mrow + (grp & 1) * 8;
#pragma unroll
        for (int kt = 0; kt < 2; kt++) {
            ldsm4t(ahi[kt], KTs + (kt * 16 + ar) * KT_PITCH + acl);
            ldsm4t(alo[kt], KTs + (32 + kt * 16 + ar) * KT_PITCH + acl);
        }
    }

    float m[2] = {-1e30f, -1e30f}, l[2] = {0.f, 0.f};
    float acc[4][4];
#pragma unroll
    for (int nt = 0; nt < 4; nt++)
#pragma unroll
        for (int e = 0; e < 4; e++) acc[nt][e] = 0.f;

    const int bkr = (grp & 1) * 8 + l8;
    const int bnc = (grp >> 1) * 8;
    const int pnr = (grp >> 1) * 8 + l8;
    const int pkc = (grp & 1) * 8;

    for (int it = 0; it < 32; it++) {
        const __half* Vh = VTs + ((it & 1) * 2) * VT_ELEMS;
        const __half* Vl = Vh + VT_ELEMS;

#pragma unroll
        for (int half = 0; half < 2; half++) {
            const int jh = half * 64;
            float S[8][4];
#pragma unroll
            for (int jt = 0; jt < 8; jt++)
#pragma unroll
                for (int e = 0; e < 4; e++) S[jt][e] = 0.f;

            // ---- S = Khi.Vhi + Khi.Vlo + Klo.Vhi (fp16, log2-scaled) ----
#pragma unroll
            for (int g = 0; g < 4; g++) {
                const int n0 = jh + g * 16 + bnc;
                uint bh0[4], bh1[4], bl0[4], bl1[4];
                ldsm4t(bh0, Vh + (bkr)      * VT_PITCH + n0);
                ldsm4t(bh1, Vh + (16 + bkr) * VT_PITCH + n0);
                ldsm4t(bl0, Vl + (bkr)      * VT_PITCH + n0);
                ldsm4t(bl1, Vl + (16 + bkr) * VT_PITCH + n0);
                float* s0 = S[2 * g];
                float* s1 = S[2 * g + 1];
                mma16816h(s0, ahi[0], bh0[0], bh0[1]); mma16816h(s0, ahi[1], bh1[0], bh1[1]);
                mma16816h(s0, ahi[0], bl0[0], bl0[1]); mma16816h(s0, ahi[1], bl1[0], bl1[1]);
                mma16816h(s0, alo[0], bh0[0], bh0[1]); mma16816h(s0, alo[1], bh1[0], bh1[1]);
                mma16816h(s1, ahi[0], bh0[2], bh0[3]); mma16816h(s1, ahi[1], bh1[2], bh1[3]);
                mma16816h(s1, ahi[0], bl0[2], bl0[3]); mma16816h(s1, ahi[1], bl1[2], bl1[3]);
                mma16816h(s1, alo[0], bh0[2], bh0[3]); mma16816h(s1, alo[1], bh1[2], bh1[3]);
            }

            // ---- online softmax (base 2) ----
#pragma unroll
            for (int r = 0; r < 2; r++) {
                float mx = -1e30f;
#pragma unroll
                for (int jt = 0; jt < 8; jt++)
                    mx = fmaxf(mx, fmaxf(S[jt][2 * r], S[jt][2 * r + 1]));
                mx = fmaxf(mx, __shfl_xor_sync(0xffffffffu, mx, 1));
                mx = fmaxf(mx, __shfl_xor_sync(0xffffffffu, mx, 2));
                float mnew  = fmaxf(m[r], mx);
                float alpha = exp2f(m[r] - mnew);
                m[r] = mnew;
                float rs = 0.f;
#pragma unroll
                for (int jt = 0; jt < 8; jt++) {
                    float e0 = exp2f(S[jt][2 * r] - mnew);
                    float e1 = exp2f(S[jt][2 * r + 1] - mnew);
                    S[jt][2 * r] = e0; S[jt][2 * r + 1] = e1;
                    rs += e0 + e1;
                }
                rs += __shfl_xor_sync(0xffffffffu, rs, 1);
                rs += __shfl_xor_sync(0xffffffffu, rs, 2);
                l[r] = l[r] * alpha + rs;
#pragma unroll
                for (int nt = 0; nt < 4; nt++) {
                    acc[nt][2 * r]     *= alpha;
                    acc[nt][2 * r + 1] *= alpha;
                }
            }

            // ---- PV: acc += P_f16 . Vhi_f16 ----
#pragma unroll
            for (int cch = 0; cch < 4; cch++) {
                float* t0 = S[2 * cch];
                float* t1 = S[2 * cch + 1];
                uint ah[4];
                ah[0] = packh(t0[0], t0[1]);
                ah[1] = packh(t0[2], t0[3]);
                ah[2] = packh(t1[0], t1[1]);
                ah[3] = packh(t1[2], t1[3]);
                const int k0 = jh + cch * 16 + pkc;
#pragma unroll
                for (int qq = 0; qq < 2; qq++) {
                    uint rh[4];
                    ldsm4(rh, Vh + (qq * 16 + pnr) * VT_PITCH + k0);
                    mma16816h(acc[2 * qq],     ah, rh[0], rh[1]);
                    mma16816h(acc[2 * qq + 1], ah, rh[2], rh[3]);
                }
            }
        }

        __syncthreads();
        if (it + 2 < 32) prefetch((it + 2) & 1, (it + 2) * 128);
        asm volatile("cp.async.commit_group;");
        asm volatile("cp.async.wait_group 1;");
        __syncthreads();
    }

    const int b = p >> 2, h = p & 3;
    int row0 = i0 + mrow + (lane >> 2);
    int row1 = row0 + 8;
    float inv0 = 1.f / l[0], inv1 = 1.f / l[1];
#pragma unroll
    for (int nt = 0; nt < 4; nt++) {
#pragma unroll
        for (int e = 0; e < 2; e++) {
            int dhh = nt * 8 + (lane & 3) * 2 + e;
            g_O[((size_t)b * SEQ + row0) * 128 + dhh * 4 + h] = acc[nt][e] * inv0;
            g_O[((size_t)b * SEQ + row1) * 128 + dhh * 4 + h] = acc[nt][2 + e] * inv1;
        }
    }
}

// ---------------------------------------------------------------------------
// Kernel 3: y = O @ w_out + b_out (3-term bf16 HMMA); grid (128, 2)
// ---------------------------------------------------------------------------
__global__ __launch_bounds__(256, 1) void proj_out_tc(const float* __restrict__ b_out,
                                                      float* __restrict__ y) {
    extern __shared__ char sm[];
    __nv_bfloat16* Xhi = (__nv_bfloat16*)sm;
    __nv_bfloat16* Xlo = Xhi + 128 * XP;
    __nv_bfloat16* Wh  = Xlo + 128 * XP;
    __nv_bfloat16* Wl  = Wh + 128 * WP;
    float* SF = (float*)Wh;

    const int row0 = blockIdx.x * 128;
    const int ch   = blockIdx.y;
    const int tid  = threadIdx.x;
    const int warp = tid >> 5;
    const int lane = tid & 31;
    const int mrow = warp * 16;
    const int grp  = lane >> 3, l8 = lane & 7;
    const int bkr  = (grp & 1) * 8 + l8;
    const int bnc  = (grp >> 1) * 8;
    const int n0   = ch * 64;

    for (int t = tid; t < 2048; t += 256) {
        int which = t >> 10;
        int rem = t & 1023;
        int k = rem >> 3, q = rem & 7;
        __nv_bfloat16* dst = (which ? Wl : Wh) + k * WP + q * 8;
        const __nv_bfloat16* src = (which ? g_WOlo : g_WOhi) + k * 128 + n0 + q * 8;
        cp16(dst, src);
    }
    asm volatile("cp.async.commit_group;");

    for (int idx = tid; idx < 128 * 32; idx += 256) {
        int r = idx >> 5, c4 = idx & 31;
        float4 v = *(const float4*)&g_O[(size_t)(row0 + r) * 128 + c4 * 4];
        uint h01 = packbf(v.x, v.y), h23 = packbf(v.z, v.w);
        uint l01 = packlo(v.x, v.y, h01), l23 = packlo(v.z, v.w, h23);
        *(uint2*)&Xhi[r * XP + c4 * 4] = make_uint2(h01, h23);
        *(uint2*)&Xlo[r * XP + c4 * 4] = make_uint2(l01, l23);
    }
    asm volatile("cp.async.wait_group 0;");
    __syncthreads();

    float acc[8][4];
#pragma unroll
    for (int t8 = 0; t8 < 8; t8++)
#pragma unroll
        for (int e = 0; e < 4; e++) acc[t8][e] = 0.f;

#pragma unroll
    for (int kc = 0; kc < 8; kc++) {
        uint ahi[4], alo[4];
        int aoff = (mrow + (lane & 15)) * XP + kc * 16 + 8 * (lane >> 4);
        ldsm4(ahi, Xhi + aoff);
        ldsm4(alo, Xlo + aoff);
#pragma unroll
        for (int g = 0; g < 4; g++) {
            uint bh[4], bl[4];
            int boff = (kc * 16 + bkr) * WP + g * 16 + bnc;
            ldsm4t(bh, Wh + boff);
            ldsm4t(bl, Wl + boff);
            float* s0 = acc[2 * g];
            float* s1 = acc[2 * g + 1];
            mma16816(s0, ahi, bh[0], bh[1]);
            mma16816(s0, ahi, bl[0], bl[1]);
            mma16816(s0, alo, bh[0], bh[1]);
            mma16816(s1, ahi, bh[2], bh[3]);
            mma16816(s1, ahi, bl[2], bl[3]);
            mma16816(s1, alo, bh[2], bh[3]);
        }
    }
    __syncthreads();

    const int r0 = mrow + (lane >> 2);
    const int q  = lane & 3;
#pragma unroll
    for (int t8 = 0; t8 < 8; t8++) {
        const int c0 = t8 * 8 + q * 2;
        float bia0 = __ldg(&b_out[n0 + c0]);
        float bia1 = __ldg(&b_out[n0 + c0 + 1]);
#pragma unroll
        for (int rr = 0; rr < 2; rr++) {
            int r = r0 + rr * 8;
            SF[r * 64 + c0]     = acc[t8][rr * 2 + 0] + bia0;
            SF[r * 64 + c0 + 1] = acc[t8][rr * 2 + 1] + bia1;
        }
    }
    __syncthreads();

    for (int idx = tid; idx < 128 * 16; idx += 256) {
        int r = idx >> 4, c4 = idx & 15;
        *(uint4*)&y[(size_t)(row0 + r) * 128 + n0 + c4 * 4] = *(uint4*)&SF[r * 64 + c4 * 4];
    }
}

// ---------------------------------------------------------------------------
extern "C" void kernel_launch(void* const* d_in, const int* in_sizes, int n_in,
                              void* d_out, int out_size) {
    const float *x = nullptr, *wq = nullptr, *wo = nullptr, *bo = nullptr;
    for (int idx = 0; idx < n_in; idx++) {
        switch (in_sizes[idx]) {
            case 4 * 16 * 256 * 128: x  = (const float*)d_in[idx]; break;
            case 128 * 384:          wq = (const float*)d_in[idx]; break;
            case 128 * 128:          wo = (const float*)d_in[idx]; break;
            case 128:                bo = (const float*)d_in[idx]; break;
        }
    }
    float* y = (float*)d_out;

    cudaFuncSetAttribute(proj_kv_tc, cudaFuncAttributeMaxDynamicSharedMemorySize, PROJ_SMEM);
    cudaFuncSetAttribute(proj_out_tc, cudaFuncAttributeMaxDynamicSharedMemorySize, PROJ_SMEM);
    cudaFuncSetAttribute(attn_kernel, cudaFuncAttributeMaxDynamicSharedMemorySize, ATTN_SMEM);

    prep_w_kernel<<<32, 256>>>(wq, wo);
    proj_kv_tc<<<dim3(128, 4), 256, PROJ_SMEM>>>(x);
    attn_kernel<<<dim3(64, NPAIR), 128, ATTN_SMEM>>>();
    proj_out_tc<<<dim3(128, 2), 256, PROJ_SMEM>>>(bo, y);
}